// round 6
// baseline (speedup 1.0000x reference)
#include <cuda_runtime.h>
#include <cuda_bf16.h>
#include <cstdint>

#define P_PERM  200000
#define PT      256
#define NTILES  ((P_PERM + PT - 1) / PT)
#define FULLM   0xffffffffu

#define SWZ(o) ((o) ^ (((o) >> 3) & 0x70))

// B operands pre-packed in mma fragment layout: per (slice, kc, nf): 32 lanes x uint4
// uint4 = {pack(h_k0,h_k1), pack(h_k8,h_k9), pack(l_k0,l_k1), pack(l_k8,l_k9)}
__device__ __align__(16) uint4 g_W1f[16 * 4 * 8 * 32];  // einsum weights, 256KB
__device__ __align__(16) uint4 g_W2f[4 * 8 * 32];       // w_lin, 16KB
__device__ __align__(16) uint4 g_W3f[2 * 4 * 8 * 32];   // w_deg1 (2 k-chunks), 32KB

// ---------------------------- SMEM layout (bytes) ---------------------------
// per-warp private tile: 8KB at warp*8192 (hi 4KB, lo 4KB)
#define SBOND 65536    // 256 f
#define SWD0  66560    // 512 f
#define SBD0  68608    // 128 f
#define SBIA  69120    // 64 f
#define SBLI  69376    // 64 f
#define SBD1  69632    // 64 f
#define SMEM_BYTES 69888

// ------------------------------ asm helpers --------------------------------
__device__ __forceinline__ void ldm_x4(uint32_t* r, uint32_t a) {
    asm volatile("ldmatrix.sync.aligned.m8n8.x4.shared.b16 {%0,%1,%2,%3}, [%4];"
                 : "=r"(r[0]), "=r"(r[1]), "=r"(r[2]), "=r"(r[3]) : "r"(a));
}
__device__ __forceinline__ void mma16816(float* d, const uint32_t* a, const uint32_t* b) {
    asm volatile(
        "mma.sync.aligned.m16n8k16.row.col.f32.bf16.bf16.f32 "
        "{%0,%1,%2,%3}, {%4,%5,%6,%7}, {%8,%9}, {%0,%1,%2,%3};"
        : "+f"(d[0]), "+f"(d[1]), "+f"(d[2]), "+f"(d[3])
        : "r"(a[0]), "r"(a[1]), "r"(a[2]), "r"(a[3]), "r"(b[0]), "r"(b[1]));
}
__device__ __forceinline__ uint32_t s2u(const void* p) {
    uint32_t a;
    asm("{ .reg .u64 t; cvta.to.shared.u64 t, %1; cvt.u32.u64 %0, t; }" : "=r"(a) : "l"(p));
    return a;
}
__device__ __forceinline__ uint32_t pack_bf2(float a, float b) {
    return (uint32_t)__bfloat16_as_ushort(__float2bfloat16(a)) |
           ((uint32_t)__bfloat16_as_ushort(__float2bfloat16(b)) << 16);
}
__device__ __forceinline__ void split_store8(const float* f, char* hd, char* ld) {
    float h[8], l[8];
    #pragma unroll
    for (int j = 0; j < 8; j++) {
        __nv_bfloat16 hb = __float2bfloat16(f[j]);
        h[j] = __bfloat162float(hb);
        l[j] = f[j] - h[j];
    }
    uint4 hv, lv;
    hv.x = pack_bf2(h[0], h[1]); hv.y = pack_bf2(h[2], h[3]);
    hv.z = pack_bf2(h[4], h[5]); hv.w = pack_bf2(h[6], h[7]);
    lv.x = pack_bf2(l[0], l[1]); lv.y = pack_bf2(l[2], l[3]);
    lv.z = pack_bf2(l[4], l[5]); lv.w = pack_bf2(l[6], l[7]);
    *(uint4*)hd = hv; *(uint4*)ld = lv;
}

// ---- per-warp m32 x n(8*NF) GEMM over K=64: acc += Xh*Wh + Xh*Wl + Xl*Wh ----
// A: warp-private swizzled tile (hi at xh, lo at xh+4096); B: gmem fragments.
template<int NF>
__device__ __forceinline__ void gemm_tile(float (&acc)[2][NF][4], uint32_t xh,
                                          const uint4* __restrict__ wf, int nf0,
                                          int lane) {
    const uint32_t xl = xh + 4096;
    const int sub = lane >> 3, rin = lane & 7;
    const uint32_t aRow = (uint32_t)(((sub & 1) << 3) + rin) * 128;
    const uint32_t aCol = (uint32_t)((sub >> 1) << 4);
    #pragma unroll
    for (int kc = 0; kc < 4; kc++) {
        uint32_t aoff = SWZ(aRow + aCol + kc * 32);
        uint32_t ah0[4], ah1[4], al0[4], al1[4];
        ldm_x4(ah0, xh + aoff);
        ldm_x4(ah1, xh + aoff + 2048);   // +16 rows
        ldm_x4(al0, xl + aoff);
        ldm_x4(al1, xl + aoff + 2048);
        #pragma unroll
        for (int nfg = 0; nfg < NF; nfg += 4) {
            uint4 bfr[4];
            #pragma unroll
            for (int q = 0; q < 4; q++)
                bfr[q] = wf[(kc * 8 + nf0 + nfg + q) * 32 + lane];
            #pragma unroll
            for (int q = 0; q < 4; q++) {
                const int nf = nfg + q;
                uint32_t bh[2] = {bfr[q].x, bfr[q].y};
                uint32_t bl[2] = {bfr[q].z, bfr[q].w};
                mma16816(acc[0][nf], ah0, bh);
                mma16816(acc[1][nf], ah1, bh);
                mma16816(acc[0][nf], ah0, bl);
                mma16816(acc[1][nf], ah1, bl);
                mma16816(acc[0][nf], al0, bh);
                mma16816(acc[1][nf], al1, bh);
            }
        }
    }
}

// ============================================================================
// prep: build B-fragment tables (hi/lo bf16 split)
// ============================================================================
__device__ __forceinline__ uint4 make_frag(float w0, float w1, float w8, float w9) {
    __nv_bfloat16 h0 = __float2bfloat16(w0), h1 = __float2bfloat16(w1);
    __nv_bfloat16 h8 = __float2bfloat16(w8), h9 = __float2bfloat16(w9);
    uint4 v;
    v.x = (uint32_t)__bfloat16_as_ushort(h0) | ((uint32_t)__bfloat16_as_ushort(h1) << 16);
    v.y = (uint32_t)__bfloat16_as_ushort(h8) | ((uint32_t)__bfloat16_as_ushort(h9) << 16);
    v.z = pack_bf2(w0 - __bfloat162float(h0), w1 - __bfloat162float(h1));
    v.w = pack_bf2(w8 - __bfloat162float(h8), w9 - __bfloat162float(h9));
    return v;
}

__global__ void prep_kernel(const float* __restrict__ weights,
                            const float* __restrict__ w_lin,
                            const float* __restrict__ w_deg1) {
    int idx = blockIdx.x * 256 + threadIdx.x;    // 0..16383
    const int lane = idx & 31;
    const int nf = (idx >> 5) & 7;
    const int kc = (idx >> 8) & 3;
    const int c = nf * 8 + (lane >> 2);
    const int kb = kc * 16 + (lane & 3) * 2;
    {
        int a = idx >> 10;
        float w0 = weights[(((kb + 0) << 6) + c) * 16 + a];
        float w1 = weights[(((kb + 1) << 6) + c) * 16 + a];
        float w8 = weights[(((kb + 8) << 6) + c) * 16 + a];
        float w9 = weights[(((kb + 9) << 6) + c) * 16 + a];
        g_W1f[idx] = make_frag(w0, w1, w8, w9);
    }
    if (idx < 1024) {
        const float* s = w_lin + c * 64;
        g_W2f[idx] = make_frag(s[kb], s[kb + 1], s[kb + 8], s[kb + 9]);
    }
    if (idx < 2048) {
        int ch = idx >> 10;
        const float* s = w_deg1 + c * 128 + ch * 64;
        g_W3f[idx] = make_frag(s[kb], s[kb + 1], s[kb + 8], s[kb + 9]);
    }
}

// ============================================================================
__global__ __launch_bounds__(256, 2)
void fused_kernel(const float* __restrict__ nfeat,
                  const float* __restrict__ degs,
                  const float* __restrict__ n2p_val,
                  const float* __restrict__ e2p_val,
                  const float* __restrict__ pool_val,
                  const float* __restrict__ bias,
                  const float* __restrict__ w_deg0,
                  const float* __restrict__ b_deg0,
                  const float* __restrict__ b_deg1,
                  const float* __restrict__ b_lin,
                  const float* __restrict__ bond_emb,
                  const int*   __restrict__ edge_feat_idx,
                  const int*   __restrict__ n2p_col,
                  const int*   __restrict__ e2p_col,
                  const int*   __restrict__ pool_row,
                  float*       __restrict__ out) {
    extern __shared__ char sm[];
    const uint32_t SB = s2u(sm);
    const int tid = threadIdx.x;
    const int warp = tid >> 5, lane = tid & 31;
    const int p0 = blockIdx.x * PT;

    float* s_bond = (float*)(sm + SBOND);
    float* s_wd0  = (float*)(sm + SWD0);
    float* s_bd0  = (float*)(sm + SBD0);
    float* s_bia  = (float*)(sm + SBIA);
    float* s_bli  = (float*)(sm + SBLI);
    float* s_bd1  = (float*)(sm + SBD1);

    for (int i = tid; i < 256; i += 256) s_bond[i] = bond_emb[i];
    for (int i = tid; i < 512; i += 256) s_wd0[i] = w_deg0[i];
    if (tid < 128) s_bd0[tid] = b_deg0[tid];
    if (tid < 64) { s_bia[tid] = bias[tid]; s_bli[tid] = b_lin[tid]; s_bd1[tid] = b_deg1[tid]; }
    __syncthreads();   // the only block-wide barrier

    char* bufc = sm + warp * 8192;          // warp-private tile (hi 4K, lo 4K)
    const uint32_t bufa = SB + warp * 8192;

    const int gp = p0 + warp * 32 + lane;   // this lane's owned permutation row
    const bool valid = gp < P_PERM;
    const int pc = valid ? gp : (P_PERM - 1);

    float acc1[2][8][4];
    #pragma unroll
    for (int m = 0; m < 2; m++)
        #pragma unroll
        for (int n = 0; n < 8; n++)
            #pragma unroll
            for (int j = 0; j < 4; j++) acc1[m][n][j] = 0.f;

    float ds[4];

    // ===================== einsum mainloop: 16 slices, per-warp ==============
    for (int ag = 0; ag < 4; ag++) {
        int4 nc4 = ((const int4*)n2p_col)[pc * 4 + ag];
        int4 ec4 = ((const int4*)e2p_col)[pc * 4 + ag];
        float4 vn4 = ((const float4*)n2p_val)[pc * 4 + ag];
        float4 ve4 = ((const float4*)e2p_val)[pc * 4 + ag];
        int   ncs[4] = {nc4.x, nc4.y, nc4.z, nc4.w};
        int   ecs[4] = {ec4.x, ec4.y, ec4.z, ec4.w};
        float vns[4] = {vn4.x, vn4.y, vn4.z, vn4.w};
        float ves[4] = {ve4.x, ve4.y, ve4.z, ve4.w};
        #pragma unroll
        for (int ai = 0; ai < 4; ai++) {
            const int a = ag * 4 + ai;
            int nc = ncs[ai];
            int bj = edge_feat_idx[ecs[ai]];
            float vn = valid ? vns[ai] : 0.f;
            float ve = valid ? ves[ai] : 0.f;
            if (ai == ag) ds[ag] = vn * degs[nc];   // slices 0,5,10,15
            #pragma unroll
            for (int pass = 0; pass < 8; pass++) {
                int r = pass * 4 + (lane >> 3);     // local row 0..31
                int   nc_r = __shfl_sync(FULLM, nc, r);
                int   bj_r = __shfl_sync(FULLM, bj, r);
                float vn_r = __shfl_sync(FULLM, vn, r);
                float ve_r = __shfl_sync(FULLM, ve, r);
                const float4* nrow = (const float4*)(nfeat + ((size_t)nc_r << 6)) + ((lane & 7) << 1);
                const float4* brow = (const float4*)(s_bond + (bj_r << 6)) + ((lane & 7) << 1);
                float4 n0 = nrow[0], n1 = nrow[1];
                float4 c0 = brow[0], c1 = brow[1];
                float f[8];
                f[0] = vn_r * n0.x + ve_r * c0.x; f[1] = vn_r * n0.y + ve_r * c0.y;
                f[2] = vn_r * n0.z + ve_r * c0.z; f[3] = vn_r * n0.w + ve_r * c0.w;
                f[4] = vn_r * n1.x + ve_r * c1.x; f[5] = vn_r * n1.y + ve_r * c1.y;
                f[6] = vn_r * n1.z + ve_r * c1.z; f[7] = vn_r * n1.w + ve_r * c1.w;
                uint32_t off = SWZ((uint32_t)r * 128 + ((lane & 7) << 4));
                split_store8(f, bufc + off, bufc + 4096 + off);
            }
            __syncwarp();
            gemm_tile<8>(acc1, bufa, g_W1f + a * 1024, 0, lane);
            __syncwarp();
        }
    }

    // ===================== relu(h)+bias -> warp tile (frees acc1) ============
    #pragma unroll
    for (int mt = 0; mt < 2; mt++)
        #pragma unroll
        for (int nf = 0; nf < 8; nf++) {
            int c0 = nf * 8 + (lane & 3) * 2;
            #pragma unroll
            for (int pr2 = 0; pr2 < 2; pr2++) {
                int r = mt * 16 + (lane >> 2) + pr2 * 8;
                float f0 = fmaxf(acc1[mt][nf][pr2 * 2 + 0] + s_bia[c0], 0.f);
                float f1 = fmaxf(acc1[mt][nf][pr2 * 2 + 1] + s_bia[c0 + 1], 0.f);
                __nv_bfloat16 h0 = __float2bfloat16(f0), h1 = __float2bfloat16(f1);
                uint32_t hv = (uint32_t)__bfloat16_as_ushort(h0) |
                              ((uint32_t)__bfloat16_as_ushort(h1) << 16);
                uint32_t lv = pack_bf2(f0 - __bfloat162float(h0), f1 - __bfloat162float(h1));
                uint32_t off = SWZ((uint32_t)r * 128 + (uint32_t)c0 * 2);
                *(uint32_t*)(bufc + off) = hv;
                *(uint32_t*)(bufc + 4096 + off) = lv;
            }
        }
    __syncwarp();

    // ===================== acc2 = relu(h) @ W2^T =============================
    float acc2[2][8][4];
    #pragma unroll
    for (int m = 0; m < 2; m++)
        #pragma unroll
        for (int n = 0; n < 8; n++)
            #pragma unroll
            for (int j = 0; j < 4; j++) acc2[m][n][j] = 0.f;
    gemm_tile<8>(acc2, bufa, g_W2f, 0, lane);
    __syncwarp();

    const float pv = valid ? pool_val[gp] : 0.f;
    const int   pr = valid ? pool_row[gp] : 0;

    // ===================== gate (n-halves, t rebuilt per half) + combine =====
    #pragma unroll
    for (int half = 0; half < 2; half++) {
        float acc3[2][4][4];
        #pragma unroll
        for (int m = 0; m < 2; m++)
            #pragma unroll
            for (int n = 0; n < 4; n++)
                #pragma unroll
                for (int j = 0; j < 4; j++) acc3[m][n][j] = 0.f;
        #pragma unroll
        for (int chunk = 0; chunk < 2; chunk++) {
            // build t chunk: lane owns local row = lane; 64 k-values
            #pragma unroll
            for (int g = 0; g < 8; g++) {
                float f[8];
                #pragma unroll
                for (int j = 0; j < 8; j++) {
                    int k = chunk * 64 + g * 8 + j;
                    float4 w = *(const float4*)&s_wd0[k * 4];
                    f[j] = fmaxf(ds[0] * w.x + ds[1] * w.y + ds[2] * w.z + ds[3] * w.w + s_bd0[k], 0.f);
                }
                uint32_t off = SWZ((uint32_t)lane * 128 + g * 16);
                split_store8(f, bufc + off, bufc + 4096 + off);
            }
            __syncwarp();
            gemm_tile<4>(acc3, bufa, g_W3f + chunk * 1024, half * 4, lane);
            __syncwarp();
        }
        // combine + scatter for this n-half
        #pragma unroll
        for (int mt = 0; mt < 2; mt++)
            #pragma unroll
            for (int fn = 0; fn < 4; fn++) {
                int nf = half * 4 + fn;
                int c0 = nf * 8 + (lane & 3) * 2;
                #pragma unroll
                for (int pr2 = 0; pr2 < 2; pr2++) {
                    int r = mt * 16 + (lane >> 2) + pr2 * 8;
                    float pv_r = __shfl_sync(FULLM, pv, r);
                    int   pr_r = __shfl_sync(FULLM, pr, r);
                    if (p0 + warp * 32 + r < P_PERM) {
                        float h2a = acc2[mt][nf][pr2 * 2 + 0] + s_bli[c0];
                        float h2b = acc2[mt][nf][pr2 * 2 + 1] + s_bli[c0 + 1];
                        float ga  = acc3[mt][fn][pr2 * 2 + 0] + s_bd1[c0];
                        float gb  = acc3[mt][fn][pr2 * 2 + 1] + s_bd1[c0 + 1];
                        atomicAdd(&out[((size_t)pr_r << 6) + c0],     pv_r * h2a * ga);
                        atomicAdd(&out[((size_t)pr_r << 6) + c0 + 1], pv_r * h2b * gb);
                    }
                }
            }
    }
}

// ============================================================================
extern "C" void kernel_launch(void* const* d_in, const int* in_sizes, int n_in,
                              void* d_out, int out_size) {
    const float* nfeat         = (const float*)d_in[0];
    const float* degs          = (const float*)d_in[1];
    const float* n2p_val       = (const float*)d_in[2];
    const float* e2p_val       = (const float*)d_in[3];
    const float* pool_val      = (const float*)d_in[4];
    const float* weights       = (const float*)d_in[5];
    const float* bias          = (const float*)d_in[6];
    const float* w_deg0        = (const float*)d_in[7];
    const float* b_deg0        = (const float*)d_in[8];
    const float* w_deg1        = (const float*)d_in[9];
    const float* b_deg1        = (const float*)d_in[10];
    const float* w_lin         = (const float*)d_in[11];
    const float* b_lin         = (const float*)d_in[12];
    const float* bond_emb      = (const float*)d_in[13];
    const int*   edge_feat_idx = (const int*)d_in[14];
    const int*   n2p_col       = (const int*)d_in[16];
    const int*   e2p_col       = (const int*)d_in[18];
    const int*   pool_row      = (const int*)d_in[19];
    float* out = (float*)d_out;

    cudaMemsetAsync(d_out, 0, (size_t)out_size * sizeof(float), 0);
    prep_kernel<<<64, 256>>>(weights, w_lin, w_deg1);

    cudaFuncSetAttribute(fused_kernel, cudaFuncAttributeMaxDynamicSharedMemorySize, SMEM_BYTES);
    fused_kernel<<<NTILES, 256, SMEM_BYTES>>>(nfeat, degs, n2p_val, e2p_val, pool_val,
                                              bias, w_deg0, b_deg0, b_deg1, b_lin,
                                              bond_emb, edge_feat_idx, n2p_col, e2p_col,
                                              pool_row, out);
}

// round 7
// speedup vs baseline: 1.8174x; 1.8174x over previous
#include <cuda_runtime.h>
#include <cuda_fp16.h>
#include <cstdint>

#define P_PERM  200000
#define PT      128
#define NTILES  ((P_PERM + PT - 1) / PT)
#define FULLM   0xffffffffu

#define SWZ(o) ((o) ^ (((o) >> 3) & 0x70))

// B operands pre-packed in fp16 mma fragment layout.
// Per (slice, kc, nfp): 32 lanes x uint4 = two n-fragments (nf = 2*nfp, 2*nfp+1):
// uint4 = {pack(e_k0,e_k1), pack(e_k8,e_k9), pack(o_k0,o_k1), pack(o_k8,o_k9)}
__device__ __align__(16) uint4 g_W1f[16 * 4 * 4 * 32];  // einsum weights, 128KB
__device__ __align__(16) uint4 g_W2f[4 * 4 * 32];       // w_lin, 8KB
__device__ __align__(16) uint4 g_W3f[2 * 4 * 4 * 32];   // w_deg1 (2 k-chunks), 16KB

// ---------------------------- SMEM layout (bytes) ---------------------------
#define XH0   0        // X tile slot0 (16KB, fp16 128x64)
#define XH1   16384    // X tile slot1
#define TH    32768    // relu(h) tile
#define SBOND 49152    // 256 f
#define SDS   50176    // 512 f
#define SWD0  52224    // 512 f
#define SBD0  54272    // 128 f
#define SBIA  54784    // 64 f
#define SBLI  55040    // 64 f
#define SBD1  55296    // 64 f
#define SPV   55552    // 128 f
#define SPR   56064    // 128 i
#define SMEM_BYTES 56576

// ------------------------------ asm helpers --------------------------------
__device__ __forceinline__ void ldm_x4(uint32_t* r, uint32_t a) {
    asm volatile("ldmatrix.sync.aligned.m8n8.x4.shared.b16 {%0,%1,%2,%3}, [%4];"
                 : "=r"(r[0]), "=r"(r[1]), "=r"(r[2]), "=r"(r[3]) : "r"(a));
}
__device__ __forceinline__ void mma16816(float* d, const uint32_t* a, uint32_t b0, uint32_t b1) {
    asm volatile(
        "mma.sync.aligned.m16n8k16.row.col.f32.f16.f16.f32 "
        "{%0,%1,%2,%3}, {%4,%5,%6,%7}, {%8,%9}, {%0,%1,%2,%3};"
        : "+f"(d[0]), "+f"(d[1]), "+f"(d[2]), "+f"(d[3])
        : "r"(a[0]), "r"(a[1]), "r"(a[2]), "r"(a[3]), "r"(b0), "r"(b1));
}
__device__ __forceinline__ uint32_t s2u(const void* p) {
    uint32_t a;
    asm("{ .reg .u64 t; cvta.to.shared.u64 t, %1; cvt.u32.u64 %0, t; }" : "=r"(a) : "l"(p));
    return a;
}
__device__ __forceinline__ uint32_t pack_h2(float a, float b) {
    __half2 h = __floats2half2_rn(a, b);
    return *(uint32_t*)&h;
}

// ---- m32 x n(16*NFP) warp GEMM over K=64, single fp16 term ------------------
// A: swizzled fp16 smem tile; B: gmem fragment pairs.
template<int NFP>
__device__ __forceinline__ void gemm_tile(float (&acc)[2][2 * NFP][4], uint32_t xh,
                                          const uint4* __restrict__ wf, int nfp0,
                                          int rbase, int lane) {
    const int sub = lane >> 3, rin = lane & 7;
    const uint32_t aRow = (uint32_t)(rbase + ((sub & 1) << 3) + rin) * 128;
    const uint32_t aCol = (uint32_t)((sub >> 1) << 4);
    #pragma unroll
    for (int kc = 0; kc < 4; kc++) {
        uint32_t aoff = SWZ(aRow + aCol + kc * 32);
        uint32_t ah0[4], ah1[4];
        ldm_x4(ah0, xh + aoff);
        ldm_x4(ah1, xh + aoff + 2048);   // +16 rows
        uint4 bfr[NFP];
        #pragma unroll
        for (int pg = 0; pg < NFP; pg++)
            bfr[pg] = wf[(kc * 4 + nfp0 + pg) * 32 + lane];
        #pragma unroll
        for (int pg = 0; pg < NFP; pg++) {
            mma16816(acc[0][2 * pg + 0], ah0, bfr[pg].x, bfr[pg].y);
            mma16816(acc[1][2 * pg + 0], ah1, bfr[pg].x, bfr[pg].y);
            mma16816(acc[0][2 * pg + 1], ah0, bfr[pg].z, bfr[pg].w);
            mma16816(acc[1][2 * pg + 1], ah1, bfr[pg].z, bfr[pg].w);
        }
    }
}

// ============================================================================
// prep: build fp16 B-fragment tables
// ============================================================================
__global__ void prep_kernel(const float* __restrict__ weights,
                            const float* __restrict__ w_lin,
                            const float* __restrict__ w_deg1) {
    int idx = blockIdx.x * 256 + threadIdx.x;    // 0..8191
    const int lane = idx & 31;
    const int nfp  = (idx >> 5) & 3;
    const int kc   = (idx >> 7) & 3;
    const int ce = nfp * 16 + (lane >> 2);       // even nf column
    const int co = ce + 8;                       // odd nf column
    const int kb = kc * 16 + (lane & 3) * 2;
    if (idx < 8192) {
        int a = idx >> 9;
        uint4 v;
        v.x = pack_h2(weights[(((kb + 0) << 6) + ce) * 16 + a],
                      weights[(((kb + 1) << 6) + ce) * 16 + a]);
        v.y = pack_h2(weights[(((kb + 8) << 6) + ce) * 16 + a],
                      weights[(((kb + 9) << 6) + ce) * 16 + a]);
        v.z = pack_h2(weights[(((kb + 0) << 6) + co) * 16 + a],
                      weights[(((kb + 1) << 6) + co) * 16 + a]);
        v.w = pack_h2(weights[(((kb + 8) << 6) + co) * 16 + a],
                      weights[(((kb + 9) << 6) + co) * 16 + a]);
        g_W1f[idx] = v;
    }
    if (idx < 512) {
        const float* se = w_lin + ce * 64;
        const float* so = w_lin + co * 64;
        uint4 v;
        v.x = pack_h2(se[kb], se[kb + 1]);
        v.y = pack_h2(se[kb + 8], se[kb + 9]);
        v.z = pack_h2(so[kb], so[kb + 1]);
        v.w = pack_h2(so[kb + 8], so[kb + 9]);
        g_W2f[idx] = v;
    }
    if (idx < 1024) {
        int ch = idx >> 9;
        const float* se = w_deg1 + ce * 128 + ch * 64;
        const float* so = w_deg1 + co * 128 + ch * 64;
        uint4 v;
        v.x = pack_h2(se[kb], se[kb + 1]);
        v.y = pack_h2(se[kb + 8], se[kb + 9]);
        v.z = pack_h2(so[kb], so[kb + 1]);
        v.w = pack_h2(so[kb + 8], so[kb + 9]);
        g_W3f[idx] = v;
    }
}

// ============================================================================
// fused: warp-specialized (4 consumer + 4 producer warps), fp16 single-term
// ============================================================================
__global__ __launch_bounds__(256, 2)
void fused_kernel(const float* __restrict__ nfeat,
                  const float* __restrict__ degs,
                  const float* __restrict__ n2p_val,
                  const float* __restrict__ e2p_val,
                  const float* __restrict__ pool_val,
                  const float* __restrict__ bias,
                  const float* __restrict__ w_deg0,
                  const float* __restrict__ b_deg0,
                  const float* __restrict__ b_deg1,
                  const float* __restrict__ b_lin,
                  const float* __restrict__ bond_emb,
                  const int*   __restrict__ edge_feat_idx,
                  const int*   __restrict__ n2p_col,
                  const int*   __restrict__ e2p_col,
                  const int*   __restrict__ pool_row,
                  float*       __restrict__ out) {
    extern __shared__ char sm[];
    const uint32_t SB = s2u(sm);
    const int tid = threadIdx.x;
    const int warp = tid >> 5, lane = tid & 31;
    const int p0 = blockIdx.x * PT;

    float* s_bond = (float*)(sm + SBOND);
    float* s_ds   = (float*)(sm + SDS);
    float* s_wd0  = (float*)(sm + SWD0);
    float* s_bd0  = (float*)(sm + SBD0);
    float* s_bia  = (float*)(sm + SBIA);
    float* s_bli  = (float*)(sm + SBLI);
    float* s_bd1  = (float*)(sm + SBD1);
    float* s_pv   = (float*)(sm + SPV);
    int*   s_pr   = (int*)(sm + SPR);

    for (int i = tid; i < 256; i += 256) s_bond[i] = bond_emb[i];
    for (int i = tid; i < 512; i += 256) s_wd0[i] = w_deg0[i];
    if (tid < 128) s_bd0[tid] = b_deg0[tid];
    if (tid < 64) { s_bia[tid] = bias[tid]; s_bli[tid] = b_lin[tid]; s_bd1[tid] = b_deg1[tid]; }
    __syncthreads();

    const int rbase = (warp & 3) * 32;
    const uint32_t xbuf[2] = {SB + XH0, SB + XH1};

    float acc1[2][8][4];
    #pragma unroll
    for (int m = 0; m < 2; m++)
        #pragma unroll
        for (int n = 0; n < 8; n++)
            #pragma unroll
            for (int j = 0; j < 4; j++) acc1[m][n][j] = 0.f;

    const int p = tid - 128;                 // producer row id (warp>=4)
    const bool valid = (p0 + p) < P_PERM;
    const int pc = valid ? (p0 + p) : (P_PERM - 1);

    // ===================== einsum mainloop (16 slices, double-buffered) ======
    for (int ag = 0; ag < 4; ag++) {
        int ncs[4], ecs[4];
        float vns[4], ves[4];
        if (warp >= 4) {
            int4 nc4 = ((const int4*)n2p_col)[pc * 4 + ag];
            int4 ec4 = ((const int4*)e2p_col)[pc * 4 + ag];
            float4 vn4 = ((const float4*)n2p_val)[pc * 4 + ag];
            float4 ve4 = ((const float4*)e2p_val)[pc * 4 + ag];
            ncs[0] = nc4.x; ncs[1] = nc4.y; ncs[2] = nc4.z; ncs[3] = nc4.w;
            ecs[0] = ec4.x; ecs[1] = ec4.y; ecs[2] = ec4.z; ecs[3] = ec4.w;
            vns[0] = vn4.x; vns[1] = vn4.y; vns[2] = vn4.z; vns[3] = vn4.w;
            ves[0] = ve4.x; ves[1] = ve4.y; ves[2] = ve4.z; ves[3] = ve4.w;
        }
        #pragma unroll
        for (int ai = 0; ai < 4; ai++) {
            const int a = ag * 4 + ai;
            const int b = a & 1;
            if (warp >= 4) {
                int nc = ncs[ai];
                int bj = edge_feat_idx[ecs[ai]];
                float vn = valid ? vns[ai] : 0.f;
                float ve = valid ? ves[ai] : 0.f;
                if (ai == ag) s_ds[p * 4 + ag] = vn * degs[nc];  // slices 0,5,10,15
                char* xh = sm + (b ? XH1 : XH0);
                const int r0 = (warp - 4) * 32;
                #pragma unroll
                for (int pass = 0; pass < 8; pass++) {
                    int src = pass * 4 + (lane >> 3);
                    int   nc_r = __shfl_sync(FULLM, nc, src);
                    int   bj_r = __shfl_sync(FULLM, bj, src);
                    float vn_r = __shfl_sync(FULLM, vn, src);
                    float ve_r = __shfl_sync(FULLM, ve, src);
                    int row = r0 + pass * 4 + (lane >> 3);
                    const float4* nrow = (const float4*)(nfeat + ((size_t)nc_r << 6)) + ((lane & 7) << 1);
                    const float4* brow = (const float4*)(s_bond + (bj_r << 6)) + ((lane & 7) << 1);
                    float4 n0 = nrow[0], n1 = nrow[1];
                    float4 c0 = brow[0], c1 = brow[1];
                    uint4 v;
                    v.x = pack_h2(vn_r * n0.x + ve_r * c0.x, vn_r * n0.y + ve_r * c0.y);
                    v.y = pack_h2(vn_r * n0.z + ve_r * c0.z, vn_r * n0.w + ve_r * c0.w);
                    v.z = pack_h2(vn_r * n1.x + ve_r * c1.x, vn_r * n1.y + ve_r * c1.y);
                    v.w = pack_h2(vn_r * n1.z + ve_r * c1.z, vn_r * n1.w + ve_r * c1.w);
                    uint32_t off = SWZ((uint32_t)row * 128 + ((lane & 7) << 4));
                    *(uint4*)(xh + off) = v;
                }
            } else if (a > 0) {
                gemm_tile<4>(acc1, xbuf[b ^ 1], g_W1f + (a - 1) * 512, 0, rbase, lane);
            }
            __syncthreads();
        }
    }

    // ===================== epilogue phase A ==================================
    // consumers: gemm slice15 (X1), relu(acc1+bias) -> TH
    // producers: t0 (k 0..63) -> X0, pool staging
    if (warp < 4) {
        gemm_tile<4>(acc1, xbuf[1], g_W1f + 15 * 512, 0, rbase, lane);
        #pragma unroll
        for (int mt = 0; mt < 2; mt++)
            #pragma unroll
            for (int nf = 0; nf < 8; nf++) {
                int c0 = nf * 8 + (lane & 3) * 2;
                #pragma unroll
                for (int pr2 = 0; pr2 < 2; pr2++) {
                    int row = rbase + mt * 16 + (lane >> 2) + pr2 * 8;
                    float f0 = fmaxf(acc1[mt][nf][pr2 * 2 + 0] + s_bia[c0], 0.f);
                    float f1 = fmaxf(acc1[mt][nf][pr2 * 2 + 1] + s_bia[c0 + 1], 0.f);
                    uint32_t off = SWZ((uint32_t)row * 128 + (uint32_t)c0 * 2);
                    *(uint32_t*)(sm + TH + off) = pack_h2(f0, f1);
                }
            }
    } else {
        float4 dv = *(const float4*)&s_ds[p * 4];
        #pragma unroll
        for (int g = 0; g < 8; g++) {
            float f[8];
            #pragma unroll
            for (int j = 0; j < 8; j++) {
                int k = g * 8 + j;
                float4 w = *(const float4*)&s_wd0[k * 4];
                f[j] = fmaxf(dv.x * w.x + dv.y * w.y + dv.z * w.z + dv.w * w.w + s_bd0[k], 0.f);
            }
            uint4 v;
            v.x = pack_h2(f[0], f[1]); v.y = pack_h2(f[2], f[3]);
            v.z = pack_h2(f[4], f[5]); v.w = pack_h2(f[6], f[7]);
            uint32_t off = SWZ((uint32_t)p * 128 + g * 16);
            *(uint4*)(sm + XH0 + off) = v;
        }
        s_pv[p] = valid ? pool_val[p0 + p] : 0.f;
        s_pr[p] = valid ? pool_row[p0 + p] : 0;
    }
    __syncthreads();

    // ===================== epilogue phase B ==================================
    // consumers: acc2 = relu(h) @ W2^T (reads TH); producers: t1 (k 64..127) -> X1
    float acc2[2][8][4];
    if (warp < 4) {
        #pragma unroll
        for (int m = 0; m < 2; m++)
            #pragma unroll
            for (int n = 0; n < 8; n++)
                #pragma unroll
                for (int j = 0; j < 4; j++) acc2[m][n][j] = 0.f;
        gemm_tile<4>(acc2, SB + TH, g_W2f, 0, rbase, lane);
    } else {
        float4 dv = *(const float4*)&s_ds[p * 4];
        #pragma unroll
        for (int g = 0; g < 8; g++) {
            float f[8];
            #pragma unroll
            for (int j = 0; j < 8; j++) {
                int k = 64 + g * 8 + j;
                float4 w = *(const float4*)&s_wd0[k * 4];
                f[j] = fmaxf(dv.x * w.x + dv.y * w.y + dv.z * w.z + dv.w * w.w + s_bd0[k], 0.f);
            }
            uint4 v;
            v.x = pack_h2(f[0], f[1]); v.y = pack_h2(f[2], f[3]);
            v.z = pack_h2(f[4], f[5]); v.w = pack_h2(f[6], f[7]);
            uint32_t off = SWZ((uint32_t)p * 128 + g * 16);
            *(uint4*)(sm + XH1 + off) = v;
        }
    }
    __syncthreads();

    // ===================== epilogue phase C: gate, combine, scatter ==========
    if (warp < 4) {
        #pragma unroll
        for (int half = 0; half < 2; half++) {
            float acc3[2][4][4];
            #pragma unroll
            for (int m = 0; m < 2; m++)
                #pragma unroll
                for (int n = 0; n < 4; n++)
                    #pragma unroll
                    for (int j = 0; j < 4; j++) acc3[m][n][j] = 0.f;
            gemm_tile<2>(acc3, SB + XH0, g_W3f, half * 2, rbase, lane);        // t0 x W3 chunk0
            gemm_tile<2>(acc3, SB + XH1, g_W3f + 512, half * 2, rbase, lane);  // t1 x W3 chunk1
            #pragma unroll
            for (int mt = 0; mt < 2; mt++)
                #pragma unroll
                for (int fn = 0; fn < 4; fn++) {
                    int nf = half * 4 + fn;
                    int c0 = nf * 8 + (lane & 3) * 2;
                    #pragma unroll
                    for (int pr2 = 0; pr2 < 2; pr2++) {
                        int row = rbase + mt * 16 + (lane >> 2) + pr2 * 8;
                        if (p0 + row < P_PERM) {
                            float pv = s_pv[row];
                            int pr = s_pr[row];
                            float h2a = acc2[mt][nf][pr2 * 2 + 0] + s_bli[c0];
                            float h2b = acc2[mt][nf][pr2 * 2 + 1] + s_bli[c0 + 1];
                            float ga  = acc3[mt][fn][pr2 * 2 + 0] + s_bd1[c0];
                            float gb  = acc3[mt][fn][pr2 * 2 + 1] + s_bd1[c0 + 1];
                            atomicAdd(&out[((size_t)pr << 6) + c0],     pv * h2a * ga);
                            atomicAdd(&out[((size_t)pr << 6) + c0 + 1], pv * h2b * gb);
                        }
                    }
                }
        }
    }
}

// ============================================================================
extern "C" void kernel_launch(void* const* d_in, const int* in_sizes, int n_in,
                              void* d_out, int out_size) {
    const float* nfeat         = (const float*)d_in[0];
    const float* degs          = (const float*)d_in[1];
    const float* n2p_val       = (const float*)d_in[2];
    const float* e2p_val       = (const float*)d_in[3];
    const float* pool_val      = (const float*)d_in[4];
    const float* weights       = (const float*)d_in[5];
    const float* bias          = (const float*)d_in[6];
    const float* w_deg0        = (const float*)d_in[7];
    const float* b_deg0        = (const float*)d_in[8];
    const float* w_deg1        = (const float*)d_in[9];
    const float* b_deg1        = (const float*)d_in[10];
    const float* w_lin         = (const float*)d_in[11];
    const float* b_lin         = (const float*)d_in[12];
    const float* bond_emb      = (const float*)d_in[13];
    const int*   edge_feat_idx = (const int*)d_in[14];
    const int*   n2p_col       = (const int*)d_in[16];
    const int*   e2p_col       = (const int*)d_in[18];
    const int*   pool_row      = (const int*)d_in[19];
    float* out = (float*)d_out;

    cudaMemsetAsync(d_out, 0, (size_t)out_size * sizeof(float), 0);
    prep_kernel<<<32, 256>>>(weights, w_lin, w_deg1);

    cudaFuncSetAttribute(fused_kernel, cudaFuncAttributeMaxDynamicSharedMemorySize, SMEM_BYTES);
    fused_kernel<<<NTILES, 256, SMEM_BYTES>>>(nfeat, degs, n2p_val, e2p_val, pool_val,
                                              bias, w_deg0, b_deg0, b_deg1, b_lin,
                                              bond_emb, edge_feat_idx, n2p_col, e2p_col,
                                              pool_row, out);
}

// round 8
// speedup vs baseline: 2.1480x; 1.1819x over previous
#include <cuda_runtime.h>
#include <cuda_fp16.h>
#include <cstdint>

#define P_PERM  200000
#define N_NODES 100000
#define PT      128
#define NTILES  ((P_PERM + PT - 1) / PT)
#define FULLM   0xffffffffu

#define SWZ(o) ((o) ^ (((o) >> 3) & 0x70))

// B operands pre-packed in fp16 mma fragment layout.
// Per (slice, kc, nfp): 32 lanes x uint4 = two n-fragments (nf = 2*nfp, 2*nfp+1)
__device__ __align__(16) uint4 g_W1f[16 * 4 * 4 * 32];  // einsum weights, 128KB
__device__ __align__(16) uint4 g_W2f[4 * 4 * 32];       // w_lin, 8KB
__device__ __align__(16) uint4 g_W3f[2 * 4 * 4 * 32];   // w_deg1 (2 k-chunks), 16KB
// nfeat converted to fp16: row-major, 8 uint4 per row (64 fp16 = 128B)
__device__ __align__(16) uint4 g_nfh[(size_t)N_NODES * 8];   // 12.8MB

// ---------------------------- SMEM layout (bytes) ---------------------------
#define XH0   0        // X tile slot0 (16KB, fp16 128x64)
#define XH1   16384    // X tile slot1
#define TH    32768    // relu(h) tile
#define SBOND 49152    // 512B: bond_emb as fp16, uint4[32]
#define SDS   50176    // 512 f
#define SWD0  52224    // 512 f
#define SBD0  54272    // 128 f
#define SBIA  54784    // 64 f
#define SBLI  55040    // 64 f
#define SBD1  55296    // 64 f
#define SPV   55552    // 128 f
#define SPR   56064    // 128 i
#define SMEM_BYTES 56576

// ------------------------------ asm helpers --------------------------------
__device__ __forceinline__ void ldm_x4(uint32_t* r, uint32_t a) {
    asm volatile("ldmatrix.sync.aligned.m8n8.x4.shared.b16 {%0,%1,%2,%3}, [%4];"
                 : "=r"(r[0]), "=r"(r[1]), "=r"(r[2]), "=r"(r[3]) : "r"(a));
}
__device__ __forceinline__ void mma16816(float* d, const uint32_t* a, uint32_t b0, uint32_t b1) {
    asm volatile(
        "mma.sync.aligned.m16n8k16.row.col.f32.f16.f16.f32 "
        "{%0,%1,%2,%3}, {%4,%5,%6,%7}, {%8,%9}, {%0,%1,%2,%3};"
        : "+f"(d[0]), "+f"(d[1]), "+f"(d[2]), "+f"(d[3])
        : "r"(a[0]), "r"(a[1]), "r"(a[2]), "r"(a[3]), "r"(b0), "r"(b1));
}
__device__ __forceinline__ uint32_t s2u(const void* p) {
    uint32_t a;
    asm("{ .reg .u64 t; cvta.to.shared.u64 t, %1; cvt.u32.u64 %0, t; }" : "=r"(a) : "l"(p));
    return a;
}
__device__ __forceinline__ uint32_t pack_h2(float a, float b) {
    __half2 h = __floats2half2_rn(a, b);
    return *(uint32_t*)&h;
}
__device__ __forceinline__ float2 h2f(uint32_t u) {
    return __half22float2(*(__half2*)&u);
}

// ---- m32 x n(16*NFP) warp GEMM over K=64, single fp16 term ------------------
template<int NFP>
__device__ __forceinline__ void gemm_tile(float (&acc)[2][2 * NFP][4], uint32_t xh,
                                          const uint4* __restrict__ wf, int nfp0,
                                          int rbase, int lane) {
    const int sub = lane >> 3, rin = lane & 7;
    const uint32_t aRow = (uint32_t)(rbase + ((sub & 1) << 3) + rin) * 128;
    const uint32_t aCol = (uint32_t)((sub >> 1) << 4);
    #pragma unroll
    for (int kc = 0; kc < 4; kc++) {
        uint32_t aoff = SWZ(aRow + aCol + kc * 32);
        uint32_t ah0[4], ah1[4];
        ldm_x4(ah0, xh + aoff);
        ldm_x4(ah1, xh + aoff + 2048);   // +16 rows
        uint4 bfr[NFP];
        #pragma unroll
        for (int pg = 0; pg < NFP; pg++)
            bfr[pg] = wf[(kc * 4 + nfp0 + pg) * 32 + lane];
        #pragma unroll
        for (int pg = 0; pg < NFP; pg++) {
            mma16816(acc[0][2 * pg + 0], ah0, bfr[pg].x, bfr[pg].y);
            mma16816(acc[1][2 * pg + 0], ah1, bfr[pg].x, bfr[pg].y);
            mma16816(acc[0][2 * pg + 1], ah0, bfr[pg].z, bfr[pg].w);
            mma16816(acc[1][2 * pg + 1], ah1, bfr[pg].z, bfr[pg].w);
        }
    }
}

// ============================================================================
// prep: build fp16 B-fragment tables + fp16 nfeat table
// ============================================================================
__global__ void prep_kernel(const float* __restrict__ weights,
                            const float* __restrict__ w_lin,
                            const float* __restrict__ w_deg1,
                            const float* __restrict__ nfeat) {
    int idx = blockIdx.x * 256 + threadIdx.x;
    if (idx < 8192) {
        const int lane = idx & 31;
        const int nfp  = (idx >> 5) & 3;
        const int kc   = (idx >> 7) & 3;
        const int ce = nfp * 16 + (lane >> 2);
        const int co = ce + 8;
        const int kb = kc * 16 + (lane & 3) * 2;
        {
            int a = idx >> 9;
            uint4 v;
            v.x = pack_h2(weights[(((kb + 0) << 6) + ce) * 16 + a],
                          weights[(((kb + 1) << 6) + ce) * 16 + a]);
            v.y = pack_h2(weights[(((kb + 8) << 6) + ce) * 16 + a],
                          weights[(((kb + 9) << 6) + ce) * 16 + a]);
            v.z = pack_h2(weights[(((kb + 0) << 6) + co) * 16 + a],
                          weights[(((kb + 1) << 6) + co) * 16 + a]);
            v.w = pack_h2(weights[(((kb + 8) << 6) + co) * 16 + a],
                          weights[(((kb + 9) << 6) + co) * 16 + a]);
            g_W1f[idx] = v;
        }
        if (idx < 512) {
            const float* se = w_lin + ce * 64;
            const float* so = w_lin + co * 64;
            uint4 v;
            v.x = pack_h2(se[kb], se[kb + 1]);
            v.y = pack_h2(se[kb + 8], se[kb + 9]);
            v.z = pack_h2(so[kb], so[kb + 1]);
            v.w = pack_h2(so[kb + 8], so[kb + 9]);
            g_W2f[idx] = v;
        }
        if (idx < 1024) {
            int ch = idx >> 9;
            const float* se = w_deg1 + ce * 128 + ch * 64;
            const float* so = w_deg1 + co * 128 + ch * 64;
            uint4 v;
            v.x = pack_h2(se[kb], se[kb + 1]);
            v.y = pack_h2(se[kb + 8], se[kb + 9]);
            v.z = pack_h2(so[kb], so[kb + 1]);
            v.w = pack_h2(so[kb + 8], so[kb + 9]);
            g_W3f[idx] = v;
        }
    } else {
        int j = idx - 8192;                 // 0 .. N_NODES*8-1
        if (j < N_NODES * 8) {
            const float4* src = (const float4*)(nfeat) + (size_t)j * 2;
            float4 a = src[0], b = src[1];
            uint4 v;
            v.x = pack_h2(a.x, a.y); v.y = pack_h2(a.z, a.w);
            v.z = pack_h2(b.x, b.y); v.w = pack_h2(b.z, b.w);
            g_nfh[j] = v;
        }
    }
}

// ============================================================================
// fused: warp-specialized (4 consumer + 4 producer warps), fp16 single-term
// ============================================================================
__global__ __launch_bounds__(256, 2)
void fused_kernel(const float* __restrict__ degs,
                  const float* __restrict__ n2p_val,
                  const float* __restrict__ e2p_val,
                  const float* __restrict__ pool_val,
                  const float* __restrict__ bias,
                  const float* __restrict__ w_deg0,
                  const float* __restrict__ b_deg0,
                  const float* __restrict__ b_deg1,
                  const float* __restrict__ b_lin,
                  const float* __restrict__ bond_emb,
                  const int*   __restrict__ edge_feat_idx,
                  const int*   __restrict__ n2p_col,
                  const int*   __restrict__ e2p_col,
                  const int*   __restrict__ pool_row,
                  float*       __restrict__ out) {
    extern __shared__ char sm[];
    const uint32_t SB = s2u(sm);
    const int tid = threadIdx.x;
    const int warp = tid >> 5, lane = tid & 31;
    const int p0 = blockIdx.x * PT;

    uint4* s_bondh = (uint4*)(sm + SBOND);
    float* s_ds   = (float*)(sm + SDS);
    float* s_wd0  = (float*)(sm + SWD0);
    float* s_bd0  = (float*)(sm + SBD0);
    float* s_bia  = (float*)(sm + SBIA);
    float* s_bli  = (float*)(sm + SBLI);
    float* s_bd1  = (float*)(sm + SBD1);
    float* s_pv   = (float*)(sm + SPV);
    int*   s_pr   = (int*)(sm + SPR);

    if (tid < 32) {   // bond_emb -> fp16, 4 rows x 8 uint4
        int row = tid >> 3, c8 = tid & 7;
        const float* s = bond_emb + row * 64 + c8 * 8;
        uint4 v;
        v.x = pack_h2(s[0], s[1]); v.y = pack_h2(s[2], s[3]);
        v.z = pack_h2(s[4], s[5]); v.w = pack_h2(s[6], s[7]);
        s_bondh[tid] = v;
    }
    for (int i = tid; i < 512; i += 256) s_wd0[i] = w_deg0[i];
    if (tid < 128) s_bd0[tid] = b_deg0[tid];
    if (tid < 64) { s_bia[tid] = bias[tid]; s_bli[tid] = b_lin[tid]; s_bd1[tid] = b_deg1[tid]; }
    __syncthreads();

    const int rbase = (warp & 3) * 32;
    const uint32_t xbuf[2] = {SB + XH0, SB + XH1};

    float acc1[2][8][4];
    #pragma unroll
    for (int m = 0; m < 2; m++)
        #pragma unroll
        for (int n = 0; n < 8; n++)
            #pragma unroll
            for (int j = 0; j < 4; j++) acc1[m][n][j] = 0.f;

    const int p = tid - 128;                 // producer row id (warp>=4)
    const bool valid = (p0 + p) < P_PERM;
    const int pc = valid ? (p0 + p) : (P_PERM - 1);

    // ===================== einsum mainloop (16 slices, double-buffered) ======
    for (int ag = 0; ag < 4; ag++) {
        int ncs[4], ecs[4];
        float vns[4], ves[4];
        if (warp >= 4) {
            int4 nc4 = ((const int4*)n2p_col)[pc * 4 + ag];
            int4 ec4 = ((const int4*)e2p_col)[pc * 4 + ag];
            float4 vn4 = ((const float4*)n2p_val)[pc * 4 + ag];
            float4 ve4 = ((const float4*)e2p_val)[pc * 4 + ag];
            ncs[0] = nc4.x; ncs[1] = nc4.y; ncs[2] = nc4.z; ncs[3] = nc4.w;
            ecs[0] = ec4.x; ecs[1] = ec4.y; ecs[2] = ec4.z; ecs[3] = ec4.w;
            vns[0] = vn4.x; vns[1] = vn4.y; vns[2] = vn4.z; vns[3] = vn4.w;
            ves[0] = ve4.x; ves[1] = ve4.y; ves[2] = ve4.z; ves[3] = ve4.w;
        }
        #pragma unroll
        for (int ai = 0; ai < 4; ai++) {
            const int a = ag * 4 + ai;
            const int b = a & 1;
            if (warp >= 4) {
                int nc = ncs[ai];
                int bj = edge_feat_idx[ecs[ai]];
                float vn = valid ? vns[ai] : 0.f;
                float ve = valid ? ves[ai] : 0.f;
                if (ai == ag) s_ds[p * 4 + ag] = vn * degs[nc];  // slices 0,5,10,15
                char* xh = sm + (b ? XH1 : XH0);
                const int r0 = (warp - 4) * 32;
                #pragma unroll
                for (int pass = 0; pass < 8; pass++) {
                    int src = pass * 4 + (lane >> 3);
                    int   nc_r = __shfl_sync(FULLM, nc, src);
                    int   bj_r = __shfl_sync(FULLM, bj, src);
                    float vn_r = __shfl_sync(FULLM, vn, src);
                    float ve_r = __shfl_sync(FULLM, ve, src);
                    int row = r0 + pass * 4 + (lane >> 3);
                    uint4 nv = g_nfh[(size_t)nc_r * 8 + (lane & 7)];     // 1 LDG.128
                    uint4 bv = s_bondh[bj_r * 8 + (lane & 7)];           // 1 LDS.128
                    float2 n0 = h2f(nv.x), n1 = h2f(nv.y), n2 = h2f(nv.z), n3 = h2f(nv.w);
                    float2 c0 = h2f(bv.x), c1 = h2f(bv.y), c2 = h2f(bv.z), c3 = h2f(bv.w);
                    uint4 v;
                    v.x = pack_h2(vn_r * n0.x + ve_r * c0.x, vn_r * n0.y + ve_r * c0.y);
                    v.y = pack_h2(vn_r * n1.x + ve_r * c1.x, vn_r * n1.y + ve_r * c1.y);
                    v.z = pack_h2(vn_r * n2.x + ve_r * c2.x, vn_r * n2.y + ve_r * c2.y);
                    v.w = pack_h2(vn_r * n3.x + ve_r * c3.x, vn_r * n3.y + ve_r * c3.y);
                    uint32_t off = SWZ((uint32_t)row * 128 + ((lane & 7) << 4));
                    *(uint4*)(xh + off) = v;
                }
            } else if (a > 0) {
                gemm_tile<4>(acc1, xbuf[b ^ 1], g_W1f + (a - 1) * 512, 0, rbase, lane);
            }
            __syncthreads();
        }
    }

    // ===================== epilogue phase A ==================================
    if (warp < 4) {
        gemm_tile<4>(acc1, xbuf[1], g_W1f + 15 * 512, 0, rbase, lane);
        #pragma unroll
        for (int mt = 0; mt < 2; mt++)
            #pragma unroll
            for (int nf = 0; nf < 8; nf++) {
                int c0 = nf * 8 + (lane & 3) * 2;
                #pragma unroll
                for (int pr2 = 0; pr2 < 2; pr2++) {
                    int row = rbase + mt * 16 + (lane >> 2) + pr2 * 8;
                    float f0 = fmaxf(acc1[mt][nf][pr2 * 2 + 0] + s_bia[c0], 0.f);
                    float f1 = fmaxf(acc1[mt][nf][pr2 * 2 + 1] + s_bia[c0 + 1], 0.f);
                    uint32_t off = SWZ((uint32_t)row * 128 + (uint32_t)c0 * 2);
                    *(uint32_t*)(sm + TH + off) = pack_h2(f0, f1);
                }
            }
    } else {
        float4 dv = *(const float4*)&s_ds[p * 4];
        #pragma unroll
        for (int g = 0; g < 8; g++) {
            float f[8];
            #pragma unroll
            for (int j = 0; j < 8; j++) {
                int k = g * 8 + j;
                float4 w = *(const float4*)&s_wd0[k * 4];
                f[j] = fmaxf(dv.x * w.x + dv.y * w.y + dv.z * w.z + dv.w * w.w + s_bd0[k], 0.f);
            }
            uint4 v;
            v.x = pack_h2(f[0], f[1]); v.y = pack_h2(f[2], f[3]);
            v.z = pack_h2(f[4], f[5]); v.w = pack_h2(f[6], f[7]);
            uint32_t off = SWZ((uint32_t)p * 128 + g * 16);
            *(uint4*)(sm + XH0 + off) = v;
        }
        s_pv[p] = valid ? pool_val[p0 + p] : 0.f;
        s_pr[p] = valid ? pool_row[p0 + p] : 0;
    }
    __syncthreads();

    // ===================== epilogue phase B ==================================
    float acc2[2][8][4];
    if (warp < 4) {
        #pragma unroll
        for (int m = 0; m < 2; m++)
            #pragma unroll
            for (int n = 0; n < 8; n++)
                #pragma unroll
                for (int j = 0; j < 4; j++) acc2[m][n][j] = 0.f;
        gemm_tile<4>(acc2, SB + TH, g_W2f, 0, rbase, lane);
    } else {
        float4 dv = *(const float4*)&s_ds[p * 4];
        #pragma unroll
        for (int g = 0; g < 8; g++) {
            float f[8];
            #pragma unroll
            for (int j = 0; j < 8; j++) {
                int k = 64 + g * 8 + j;
                float4 w = *(const float4*)&s_wd0[k * 4];
                f[j] = fmaxf(dv.x * w.x + dv.y * w.y + dv.z * w.z + dv.w * w.w + s_bd0[k], 0.f);
            }
            uint4 v;
            v.x = pack_h2(f[0], f[1]); v.y = pack_h2(f[2], f[3]);
            v.z = pack_h2(f[4], f[5]); v.w = pack_h2(f[6], f[7]);
            uint32_t off = SWZ((uint32_t)p * 128 + g * 16);
            *(uint4*)(sm + XH1 + off) = v;
        }
    }
    __syncthreads();

    // ===================== epilogue phase C: gate, combine, scatter ==========
    if (warp < 4) {
        #pragma unroll
        for (int half = 0; half < 2; half++) {
            float acc3[2][4][4];
            #pragma unroll
            for (int m = 0; m < 2; m++)
                #pragma unroll
                for (int n = 0; n < 4; n++)
                    #pragma unroll
                    for (int j = 0; j < 4; j++) acc3[m][n][j] = 0.f;
            gemm_tile<2>(acc3, SB + XH0, g_W3f, half * 2, rbase, lane);        // t0 x W3 chunk0
            gemm_tile<2>(acc3, SB + XH1, g_W3f + 512, half * 2, rbase, lane);  // t1 x W3 chunk1
            #pragma unroll
            for (int mt = 0; mt < 2; mt++)
                #pragma unroll
                for (int fn = 0; fn < 4; fn++) {
                    int nf = half * 4 + fn;
                    int c0 = nf * 8 + (lane & 3) * 2;
                    #pragma unroll
                    for (int pr2 = 0; pr2 < 2; pr2++) {
                        int row = rbase + mt * 16 + (lane >> 2) + pr2 * 8;
                        if (p0 + row < P_PERM) {
                            float pv = s_pv[row];
                            int pr = s_pr[row];
                            float h2a = acc2[mt][nf][pr2 * 2 + 0] + s_bli[c0];
                            float h2b = acc2[mt][nf][pr2 * 2 + 1] + s_bli[c0 + 1];
                            float ga  = acc3[mt][fn][pr2 * 2 + 0] + s_bd1[c0];
                            float gb  = acc3[mt][fn][pr2 * 2 + 1] + s_bd1[c0 + 1];
                            atomicAdd(&out[((size_t)pr << 6) + c0],     pv * h2a * ga);
                            atomicAdd(&out[((size_t)pr << 6) + c0 + 1], pv * h2b * gb);
                        }
                    }
                }
        }
    }
}

// ============================================================================
extern "C" void kernel_launch(void* const* d_in, const int* in_sizes, int n_in,
                              void* d_out, int out_size) {
    const float* nfeat         = (const float*)d_in[0];
    const float* degs          = (const float*)d_in[1];
    const float* n2p_val       = (const float*)d_in[2];
    const float* e2p_val       = (const float*)d_in[3];
    const float* pool_val      = (const float*)d_in[4];
    const float* weights       = (const float*)d_in[5];
    const float* bias          = (const float*)d_in[6];
    const float* w_deg0        = (const float*)d_in[7];
    const float* b_deg0        = (const float*)d_in[8];
    const float* w_deg1        = (const float*)d_in[9];
    const float* b_deg1        = (const float*)d_in[10];
    const float* w_lin         = (const float*)d_in[11];
    const float* b_lin         = (const float*)d_in[12];
    const float* bond_emb      = (const float*)d_in[13];
    const int*   edge_feat_idx = (const int*)d_in[14];
    const int*   n2p_col       = (const int*)d_in[16];
    const int*   e2p_col       = (const int*)d_in[18];
    const int*   pool_row      = (const int*)d_in[19];
    float* out = (float*)d_out;

    cudaMemsetAsync(d_out, 0, (size_t)out_size * sizeof(float), 0);
    // covers 8192 weight threads + 800000 nfeat-convert threads
    prep_kernel<<<(8192 + N_NODES * 8 + 255) / 256, 256>>>(weights, w_lin, w_deg1, nfeat);

    cudaFuncSetAttribute(fused_kernel, cudaFuncAttributeMaxDynamicSharedMemorySize, SMEM_BYTES);
    fused_kernel<<<NTILES, 256, SMEM_BYTES>>>(degs, n2p_val, e2p_val, pool_val,
                                              bias, w_deg0, b_deg0, b_deg1, b_lin,
                                              bond_emb, edge_feat_idx, n2p_col, e2p_col,
                                              pool_row, out);
}

// round 9
// speedup vs baseline: 2.4336x; 1.1330x over previous
#include <cuda_runtime.h>
#include <cuda_fp16.h>
#include <cstdint>

#define P_PERM  200000
#define N_NODES 100000
#define PT      128
#define NTILES  ((P_PERM + PT - 1) / PT)
#define FULLM   0xffffffffu

#define SWZ(o) ((o) ^ (((o) >> 3) & 0x70))

// B operands pre-packed in fp16 mma fragment layout.
__device__ __align__(16) uint4 g_W1f[16 * 4 * 4 * 32];  // einsum weights, 128KB
__device__ __align__(16) uint4 g_W2f[4 * 4 * 32];       // w_lin, 8KB
__device__ __align__(16) uint4 g_W3f[2 * 4 * 4 * 32];   // w_deg1 (2 k-chunks), 16KB
// nfeat converted to fp16: row-major, 8 uint4 per row (64 fp16 = 128B)
__device__ __align__(16) uint4 g_nfh[(size_t)N_NODES * 8];   // 12.8MB

// ---------------------------- SMEM layout (bytes) ---------------------------
#define XB0   0        // four 16KB fp16 X tiles (128x64)
#define XB1   16384
#define XB2   32768
#define XB3   49152
#define SBOND 65536    // 512B: bond_emb fp16, uint4[32]
#define SDS   66048    // 512 f
#define SWD0  68096    // 512 f
#define SBD0  70144    // 128 f
#define SBIA  70656    // 64 f
#define SBLI  70912    // 64 f
#define SBD1  71168    // 64 f
#define SPV   71424    // 128 f
#define SPR   71936    // 128 i
#define SMEM_BYTES 72448

// ------------------------------ asm helpers --------------------------------
__device__ __forceinline__ void ldm_x4(uint32_t* r, uint32_t a) {
    asm volatile("ldmatrix.sync.aligned.m8n8.x4.shared.b16 {%0,%1,%2,%3}, [%4];"
                 : "=r"(r[0]), "=r"(r[1]), "=r"(r[2]), "=r"(r[3]) : "r"(a));
}
__device__ __forceinline__ void mma16816(float* d, const uint32_t* a, uint32_t b0, uint32_t b1) {
    asm volatile(
        "mma.sync.aligned.m16n8k16.row.col.f32.f16.f16.f32 "
        "{%0,%1,%2,%3}, {%4,%5,%6,%7}, {%8,%9}, {%0,%1,%2,%3};"
        : "+f"(d[0]), "+f"(d[1]), "+f"(d[2]), "+f"(d[3])
        : "r"(a[0]), "r"(a[1]), "r"(a[2]), "r"(a[3]), "r"(b0), "r"(b1));
}
__device__ __forceinline__ uint32_t s2u(const void* p) {
    uint32_t a;
    asm("{ .reg .u64 t; cvta.to.shared.u64 t, %1; cvt.u32.u64 %0, t; }" : "=r"(a) : "l"(p));
    return a;
}
__device__ __forceinline__ uint32_t pack_h2(float a, float b) {
    __half2 h = __floats2half2_rn(a, b);
    return *(uint32_t*)&h;
}

// ---- m32 x n(16*NFP) warp GEMM over K=64, single fp16 term ------------------
template<int NFP>
__device__ __forceinline__ void gemm_tile(float (&acc)[2][2 * NFP][4], uint32_t xh,
                                          const uint4* __restrict__ wf, int nfp0,
                                          int rbase, int lane) {
    const int sub = lane >> 3, rin = lane & 7;
    const uint32_t aRow = (uint32_t)(rbase + ((sub & 1) << 3) + rin) * 128;
    const uint32_t aCol = (uint32_t)((sub >> 1) << 4);
    #pragma unroll
    for (int kc = 0; kc < 4; kc++) {
        uint32_t aoff = SWZ(aRow + aCol + kc * 32);
        uint32_t ah0[4], ah1[4];
        ldm_x4(ah0, xh + aoff);
        ldm_x4(ah1, xh + aoff + 2048);   // +16 rows
        uint4 bfr[NFP];
        #pragma unroll
        for (int pg = 0; pg < NFP; pg++)
            bfr[pg] = wf[(kc * 4 + nfp0 + pg) * 32 + lane];
        #pragma unroll
        for (int pg = 0; pg < NFP; pg++) {
            mma16816(acc[0][2 * pg + 0], ah0, bfr[pg].x, bfr[pg].y);
            mma16816(acc[1][2 * pg + 0], ah1, bfr[pg].x, bfr[pg].y);
            mma16816(acc[0][2 * pg + 1], ah0, bfr[pg].z, bfr[pg].w);
            mma16816(acc[1][2 * pg + 1], ah1, bfr[pg].z, bfr[pg].w);
        }
    }
}

// ============================================================================
// prep: build fp16 B-fragment tables + fp16 nfeat table
// ============================================================================
__global__ void prep_kernel(const float* __restrict__ weights,
                            const float* __restrict__ w_lin,
                            const float* __restrict__ w_deg1,
                            const float* __restrict__ nfeat) {
    int idx = blockIdx.x * 256 + threadIdx.x;
    if (idx < 8192) {
        const int lane = idx & 31;
        const int nfp  = (idx >> 5) & 3;
        const int kc   = (idx >> 7) & 3;
        const int ce = nfp * 16 + (lane >> 2);
        const int co = ce + 8;
        const int kb = kc * 16 + (lane & 3) * 2;
        {
            int a = idx >> 9;
            uint4 v;
            v.x = pack_h2(weights[(((kb + 0) << 6) + ce) * 16 + a],
                          weights[(((kb + 1) << 6) + ce) * 16 + a]);
            v.y = pack_h2(weights[(((kb + 8) << 6) + ce) * 16 + a],
                          weights[(((kb + 9) << 6) + ce) * 16 + a]);
            v.z = pack_h2(weights[(((kb + 0) << 6) + co) * 16 + a],
                          weights[(((kb + 1) << 6) + co) * 16 + a]);
            v.w = pack_h2(weights[(((kb + 8) << 6) + co) * 16 + a],
                          weights[(((kb + 9) << 6) + co) * 16 + a]);
            g_W1f[idx] = v;
        }
        if (idx < 512) {
            const float* se = w_lin + ce * 64;
            const float* so = w_lin + co * 64;
            uint4 v;
            v.x = pack_h2(se[kb], se[kb + 1]);
            v.y = pack_h2(se[kb + 8], se[kb + 9]);
            v.z = pack_h2(so[kb], so[kb + 1]);
            v.w = pack_h2(so[kb + 8], so[kb + 9]);
            g_W2f[idx] = v;
        }
        if (idx < 1024) {
            int ch = idx >> 9;
            const float* se = w_deg1 + ce * 128 + ch * 64;
            const float* so = w_deg1 + co * 128 + ch * 64;
            uint4 v;
            v.x = pack_h2(se[kb], se[kb + 1]);
            v.y = pack_h2(se[kb + 8], se[kb + 9]);
            v.z = pack_h2(so[kb], so[kb + 1]);
            v.w = pack_h2(so[kb + 8], so[kb + 9]);
            g_W3f[idx] = v;
        }
    } else {
        int j = idx - 8192;                 // 0 .. N_NODES*8-1
        if (j < N_NODES * 8) {
            const float4* src = (const float4*)(nfeat) + (size_t)j * 2;
            float4 a = src[0], b = src[1];
            uint4 v;
            v.x = pack_h2(a.x, a.y); v.y = pack_h2(a.z, a.w);
            v.z = pack_h2(b.x, b.y); v.w = pack_h2(b.z, b.w);
            g_nfh[j] = v;
        }
    }
}

// ============================================================================
// fused: warp-specialized, fp16, 2 slices per barrier epoch (4 buffers)
// ============================================================================
__global__ __launch_bounds__(256, 2)
void fused_kernel(const float* __restrict__ degs,
                  const float* __restrict__ n2p_val,
                  const float* __restrict__ e2p_val,
                  const float* __restrict__ pool_val,
                  const float* __restrict__ bias,
                  const float* __restrict__ w_deg0,
                  const float* __restrict__ b_deg0,
                  const float* __restrict__ b_deg1,
                  const float* __restrict__ b_lin,
                  const float* __restrict__ bond_emb,
                  const int*   __restrict__ edge_feat_idx,
                  const int*   __restrict__ n2p_col,
                  const int*   __restrict__ e2p_col,
                  const int*   __restrict__ pool_row,
                  float*       __restrict__ out) {
    extern __shared__ char sm[];
    const uint32_t SB = s2u(sm);
    const int tid = threadIdx.x;
    const int warp = tid >> 5, lane = tid & 31;
    const int p0 = blockIdx.x * PT;

    uint4* s_bondh = (uint4*)(sm + SBOND);
    float* s_ds   = (float*)(sm + SDS);
    float* s_wd0  = (float*)(sm + SWD0);
    float* s_bd0  = (float*)(sm + SBD0);
    float* s_bia  = (float*)(sm + SBIA);
    float* s_bli  = (float*)(sm + SBLI);
    float* s_bd1  = (float*)(sm + SBD1);
    float* s_pv   = (float*)(sm + SPV);
    int*   s_pr   = (int*)(sm + SPR);

    if (tid < 32) {   // bond_emb -> fp16, 4 rows x 8 uint4
        int row = tid >> 3, c8 = tid & 7;
        const float* s = bond_emb + row * 64 + c8 * 8;
        uint4 v;
        v.x = pack_h2(s[0], s[1]); v.y = pack_h2(s[2], s[3]);
        v.z = pack_h2(s[4], s[5]); v.w = pack_h2(s[6], s[7]);
        s_bondh[tid] = v;
    }
    for (int i = tid; i < 512; i += 256) s_wd0[i] = w_deg0[i];
    if (tid < 128) s_bd0[tid] = b_deg0[tid];
    if (tid < 64) { s_bia[tid] = bias[tid]; s_bli[tid] = b_lin[tid]; s_bd1[tid] = b_deg1[tid]; }
    __syncthreads();

    const int rbase = (warp & 3) * 32;

    float acc1[2][8][4];
    #pragma unroll
    for (int m = 0; m < 2; m++)
        #pragma unroll
        for (int n = 0; n < 8; n++)
            #pragma unroll
            for (int j = 0; j < 4; j++) acc1[m][n][j] = 0.f;

    const int p = tid - 128;                 // producer row id (warp>=4)
    const bool valid = (p0 + p) < P_PERM;
    const int pc = valid ? (p0 + p) : (P_PERM - 1);

    int ncs[4], ecs[4];
    float vns[4], ves[4];

    // ======== einsum mainloop: 8 epochs x 2 slices, 4-buffer pipeline ========
    #pragma unroll
    for (int e = 0; e < 8; e++) {
        const int pb = (e & 1) << 1;         // producer buffer pair: 0 or 2
        if (warp >= 4 && (e & 1) == 0) {     // load 4-slice index group
            int g = e >> 1;
            int4 nc4 = ((const int4*)n2p_col)[pc * 4 + g];
            int4 ec4 = ((const int4*)e2p_col)[pc * 4 + g];
            float4 vn4 = ((const float4*)n2p_val)[pc * 4 + g];
            float4 ve4 = ((const float4*)e2p_val)[pc * 4 + g];
            ncs[0] = nc4.x; ncs[1] = nc4.y; ncs[2] = nc4.z; ncs[3] = nc4.w;
            ecs[0] = ec4.x; ecs[1] = ec4.y; ecs[2] = ec4.z; ecs[3] = ec4.w;
            vns[0] = vn4.x; vns[1] = vn4.y; vns[2] = vn4.z; vns[3] = vn4.w;
            ves[0] = ve4.x; ves[1] = ve4.y; ves[2] = ve4.z; ves[3] = ve4.w;
        }
        if (warp >= 4) {
            #pragma unroll
            for (int s = 0; s < 2; s++) {
                const int a = 2 * e + s;
                const int ai = a & 3;
                int nc = ncs[ai];
                int bj = edge_feat_idx[ecs[ai]];
                float vn = valid ? vns[ai] : 0.f;
                float ve = valid ? ves[ai] : 0.f;
                if (ai == (a >> 2)) s_ds[p * 4 + (a >> 2)] = vn * degs[nc]; // a%5==0
                char* xh = sm + (pb + s) * 16384;
                const int r0 = (warp - 4) * 32;
                #pragma unroll
                for (int pass = 0; pass < 8; pass++) {
                    int src = pass * 4 + (lane >> 3);
                    int   nc_r = __shfl_sync(FULLM, nc, src);
                    int   bj_r = __shfl_sync(FULLM, bj, src);
                    float vn_r = __shfl_sync(FULLM, vn, src);
                    float ve_r = __shfl_sync(FULLM, ve, src);
                    int row = r0 + pass * 4 + (lane >> 3);
                    uint4 nv = g_nfh[(size_t)nc_r * 8 + (lane & 7)];     // 1 LDG.128
                    uint4 bv = s_bondh[bj_r * 8 + (lane & 7)];           // 1 LDS.128
                    __half2 vn2 = __float2half2_rn(vn_r);
                    __half2 ve2 = __float2half2_rn(ve_r);
                    uint4 v;
                    *(__half2*)&v.x = __hfma2(vn2, *(const __half2*)&nv.x,
                                              __hmul2(ve2, *(const __half2*)&bv.x));
                    *(__half2*)&v.y = __hfma2(vn2, *(const __half2*)&nv.y,
                                              __hmul2(ve2, *(const __half2*)&bv.y));
                    *(__half2*)&v.z = __hfma2(vn2, *(const __half2*)&nv.z,
                                              __hmul2(ve2, *(const __half2*)&bv.z));
                    *(__half2*)&v.w = __hfma2(vn2, *(const __half2*)&nv.w,
                                              __hmul2(ve2, *(const __half2*)&bv.w));
                    uint32_t off = SWZ((uint32_t)row * 128 + ((lane & 7) << 4));
                    *(uint4*)(xh + off) = v;
                }
            }
        } else if (e > 0) {
            const int cb = pb ^ 2;           // consumer buffer pair
            #pragma unroll
            for (int s = 0; s < 2; s++) {
                const int a = 2 * (e - 1) + s;
                gemm_tile<4>(acc1, SB + (cb + s) * 16384, g_W1f + a * 512, 0, rbase, lane);
            }
        }
        __syncthreads();
    }

    // ===================== epilogue phase A ==================================
    // consumers: gemm slices 14 (XB2), 15 (XB3); relu(acc1+bias) -> XB0
    // producers: t0 (k 0..63) -> XB1, pool staging
    if (warp < 4) {
        gemm_tile<4>(acc1, SB + XB2, g_W1f + 14 * 512, 0, rbase, lane);
        gemm_tile<4>(acc1, SB + XB3, g_W1f + 15 * 512, 0, rbase, lane);
        #pragma unroll
        for (int mt = 0; mt < 2; mt++)
            #pragma unroll
            for (int nf = 0; nf < 8; nf++) {
                int c0 = nf * 8 + (lane & 3) * 2;
                #pragma unroll
                for (int pr2 = 0; pr2 < 2; pr2++) {
                    int row = rbase + mt * 16 + (lane >> 2) + pr2 * 8;
                    float f0 = fmaxf(acc1[mt][nf][pr2 * 2 + 0] + s_bia[c0], 0.f);
                    float f1 = fmaxf(acc1[mt][nf][pr2 * 2 + 1] + s_bia[c0 + 1], 0.f);
                    uint32_t off = SWZ((uint32_t)row * 128 + (uint32_t)c0 * 2);
                    *(uint32_t*)(sm + XB0 + off) = pack_h2(f0, f1);
                }
            }
    } else {
        float4 dv = *(const float4*)&s_ds[p * 4];
        #pragma unroll
        for (int g = 0; g < 8; g++) {
            float f[8];
            #pragma unroll
            for (int j = 0; j < 8; j++) {
                int k = g * 8 + j;
                float4 w = *(const float4*)&s_wd0[k * 4];
                f[j] = fmaxf(dv.x * w.x + dv.y * w.y + dv.z * w.z + dv.w * w.w + s_bd0[k], 0.f);
            }
            uint4 v;
            v.x = pack_h2(f[0], f[1]); v.y = pack_h2(f[2], f[3]);
            v.z = pack_h2(f[4], f[5]); v.w = pack_h2(f[6], f[7]);
            uint32_t off = SWZ((uint32_t)p * 128 + g * 16);
            *(uint4*)(sm + XB1 + off) = v;
        }
        s_pv[p] = valid ? pool_val[p0 + p] : 0.f;
        s_pr[p] = valid ? pool_row[p0 + p] : 0;
    }
    __syncthreads();

    // ===================== epilogue phase B ==================================
    // consumers: acc2 = relu(h) @ W2^T (reads XB0); producers: t1 -> XB2
    float acc2[2][8][4];
    if (warp < 4) {
        #pragma unroll
        for (int m = 0; m < 2; m++)
            #pragma unroll
            for (int n = 0; n < 8; n++)
                #pragma unroll
                for (int j = 0; j < 4; j++) acc2[m][n][j] = 0.f;
        gemm_tile<4>(acc2, SB + XB0, g_W2f, 0, rbase, lane);
    } else {
        float4 dv = *(const float4*)&s_ds[p * 4];
        #pragma unroll
        for (int g = 0; g < 8; g++) {
            float f[8];
            #pragma unroll
            for (int j = 0; j < 8; j++) {
                int k = 64 + g * 8 + j;
                float4 w = *(const float4*)&s_wd0[k * 4];
                f[j] = fmaxf(dv.x * w.x + dv.y * w.y + dv.z * w.z + dv.w * w.w + s_bd0[k], 0.f);
            }
            uint4 v;
            v.x = pack_h2(f[0], f[1]); v.y = pack_h2(f[2], f[3]);
            v.z = pack_h2(f[4], f[5]); v.w = pack_h2(f[6], f[7]);
            uint32_t off = SWZ((uint32_t)p * 128 + g * 16);
            *(uint4*)(sm + XB2 + off) = v;
        }
    }
    __syncthreads();

    // ===================== epilogue phase C: gate, combine, scatter ==========
    if (warp < 4) {
        #pragma unroll
        for (int half = 0; half < 2; half++) {
            float acc3[2][4][4];
            #pragma unroll
            for (int m = 0; m < 2; m++)
                #pragma unroll
                for (int n = 0; n < 4; n++)
                    #pragma unroll
                    for (int j = 0; j < 4; j++) acc3[m][n][j] = 0.f;
            gemm_tile<2>(acc3, SB + XB1, g_W3f, half * 2, rbase, lane);        // t0 x W3 chunk0
            gemm_tile<2>(acc3, SB + XB2, g_W3f + 512, half * 2, rbase, lane);  // t1 x W3 chunk1
            #pragma unroll
            for (int mt = 0; mt < 2; mt++)
                #pragma unroll
                for (int fn = 0; fn < 4; fn++) {
                    int nf = half * 4 + fn;
                    int c0 = nf * 8 + (lane & 3) * 2;
                    #pragma unroll
                    for (int pr2 = 0; pr2 < 2; pr2++) {
                        int row = rbase + mt * 16 + (lane >> 2) + pr2 * 8;
                        if (p0 + row < P_PERM) {
                            float pv = s_pv[row];
                            int pr = s_pr[row];
                            float h2a = acc2[mt][nf][pr2 * 2 + 0] + s_bli[c0];
                            float h2b = acc2[mt][nf][pr2 * 2 + 1] + s_bli[c0 + 1];
                            float ga  = acc3[mt][fn][pr2 * 2 + 0] + s_bd1[c0];
                            float gb  = acc3[mt][fn][pr2 * 2 + 1] + s_bd1[c0 + 1];
                            atomicAdd(&out[((size_t)pr << 6) + c0],     pv * h2a * ga);
                            atomicAdd(&out[((size_t)pr << 6) + c0 + 1], pv * h2b * gb);
                        }
                    }
                }
        }
    }
}

// ============================================================================
extern "C" void kernel_launch(void* const* d_in, const int* in_sizes, int n_in,
                              void* d_out, int out_size) {
    const float* nfeat         = (const float*)d_in[0];
    const float* degs          = (const float*)d_in[1];
    const float* n2p_val       = (const float*)d_in[2];
    const float* e2p_val       = (const float*)d_in[3];
    const float* pool_val      = (const float*)d_in[4];
    const float* weights       = (const float*)d_in[5];
    const float* bias          = (const float*)d_in[6];
    const float* w_deg0        = (const float*)d_in[7];
    const float* b_deg0        = (const float*)d_in[8];
    const float* w_deg1        = (const float*)d_in[9];
    const float* b_deg1        = (const float*)d_in[10];
    const float* w_lin         = (const float*)d_in[11];
    const float* b_lin         = (const float*)d_in[12];
    const float* bond_emb      = (const float*)d_in[13];
    const int*   edge_feat_idx = (const int*)d_in[14];
    const int*   n2p_col       = (const int*)d_in[16];
    const int*   e2p_col       = (const int*)d_in[18];
    const int*   pool_row      = (const int*)d_in[19];
    float* out = (float*)d_out;

    cudaMemsetAsync(d_out, 0, (size_t)out_size * sizeof(float), 0);
    prep_kernel<<<(8192 + N_NODES * 8 + 255) / 256, 256>>>(weights, w_lin, w_deg1, nfeat);

    cudaFuncSetAttribute(fused_kernel, cudaFuncAttributeMaxDynamicSharedMemorySize, SMEM_BYTES);
    fused_kernel<<<NTILES, 256, SMEM_BYTES>>>(degs, n2p_val, e2p_val, pool_val,
                                              bias, w_deg0, b_deg0, b_deg1, b_lin,
                                              bond_emb, edge_feat_idx, n2p_col, e2p_col,
                                              pool_row, out);
}

// round 10
// speedup vs baseline: 2.5588x; 1.0515x over previous
#include <cuda_runtime.h>
#include <cuda_fp16.h>
#include <cstdint>

#define P_PERM  200000
#define N_NODES 100000
#define PT      128
#define NTILES  ((P_PERM + PT - 1) / PT)
#define FULLM   0xffffffffu

#define SWZ(o) ((o) ^ (((o) >> 3) & 0x70))

// named barrier ids (0 = __syncthreads)
#define BAR_FREE0 1
#define BAR_FREE1 2
#define BAR_FULL0 3
#define BAR_FULL1 4
#define BAR_SYNC(id)   asm volatile("bar.sync %0, 256;"   :: "r"(id) : "memory")
#define BAR_ARRIVE(id) asm volatile("bar.arrive %0, 256;" :: "r"(id) : "memory")

// B operands pre-packed in fp16 mma fragment layout.
__device__ __align__(16) uint4 g_W1f[16 * 4 * 4 * 32];  // einsum weights, 128KB
__device__ __align__(16) uint4 g_W2f[4 * 4 * 32];       // w_lin, 8KB
__device__ __align__(16) uint4 g_W3f[2 * 4 * 4 * 32];   // w_deg1 (2 k-chunks), 16KB
// nfeat converted to fp16: row-major, 8 uint4 per row (64 fp16 = 128B)
__device__ __align__(16) uint4 g_nfh[(size_t)N_NODES * 8];   // 12.8MB

// ---------------------------- SMEM layout (bytes) ---------------------------
#define XB0   0        // four 16KB fp16 X tiles (128x64)
#define XB1   16384
#define XB2   32768
#define XB3   49152
#define SBOND 65536    // 512B: bond_emb fp16, uint4[32]
#define SDS   66048    // 512 f
#define SWD0  68096    // 512 f
#define SBD0  70144    // 128 f
#define SBIA  70656    // 64 f
#define SBLI  70912    // 64 f
#define SBD1  71168    // 64 f
#define SPV   71424    // 128 f
#define SPR   71936    // 128 i
#define SMEM_BYTES 72448

// ------------------------------ asm helpers --------------------------------
__device__ __forceinline__ void ldm_x4(uint32_t* r, uint32_t a) {
    asm volatile("ldmatrix.sync.aligned.m8n8.x4.shared.b16 {%0,%1,%2,%3}, [%4];"
                 : "=r"(r[0]), "=r"(r[1]), "=r"(r[2]), "=r"(r[3]) : "r"(a));
}
__device__ __forceinline__ void mma16816(float* d, const uint32_t* a, uint32_t b0, uint32_t b1) {
    asm volatile(
        "mma.sync.aligned.m16n8k16.row.col.f32.f16.f16.f32 "
        "{%0,%1,%2,%3}, {%4,%5,%6,%7}, {%8,%9}, {%0,%1,%2,%3};"
        : "+f"(d[0]), "+f"(d[1]), "+f"(d[2]), "+f"(d[3])
        : "r"(a[0]), "r"(a[1]), "r"(a[2]), "r"(a[3]), "r"(b0), "r"(b1));
}
__device__ __forceinline__ uint32_t s2u(const void* p) {
    uint32_t a;
    asm("{ .reg .u64 t; cvta.to.shared.u64 t, %1; cvt.u32.u64 %0, t; }" : "=r"(a) : "l"(p));
    return a;
}
__device__ __forceinline__ uint32_t pack_h2(float a, float b) {
    __half2 h = __floats2half2_rn(a, b);
    return *(uint32_t*)&h;
}

// ---- m32 x n(16*NFP) warp GEMM over K=64, single fp16 term ------------------
template<int NFP>
__device__ __forceinline__ void gemm_tile(float (&acc)[2][2 * NFP][4], uint32_t xh,
                                          const uint4* __restrict__ wf, int nfp0,
                                          int rbase, int lane) {
    const int sub = lane >> 3, rin = lane & 7;
    const uint32_t aRow = (uint32_t)(rbase + ((sub & 1) << 3) + rin) * 128;
    const uint32_t aCol = (uint32_t)((sub >> 1) << 4);
    #pragma unroll
    for (int kc = 0; kc < 4; kc++) {
        uint32_t aoff = SWZ(aRow + aCol + kc * 32);
        uint32_t ah0[4], ah1[4];
        ldm_x4(ah0, xh + aoff);
        ldm_x4(ah1, xh + aoff + 2048);   // +16 rows
        uint4 bfr[NFP];
        #pragma unroll
        for (int pg = 0; pg < NFP; pg++)
            bfr[pg] = wf[(kc * 4 + nfp0 + pg) * 32 + lane];
        #pragma unroll
        for (int pg = 0; pg < NFP; pg++) {
            mma16816(acc[0][2 * pg + 0], ah0, bfr[pg].x, bfr[pg].y);
            mma16816(acc[1][2 * pg + 0], ah1, bfr[pg].x, bfr[pg].y);
            mma16816(acc[0][2 * pg + 1], ah0, bfr[pg].z, bfr[pg].w);
            mma16816(acc[1][2 * pg + 1], ah1, bfr[pg].z, bfr[pg].w);
        }
    }
}

// ============================================================================
// prep: build fp16 B-fragment tables + fp16 nfeat table
// ============================================================================
__global__ void prep_kernel(const float* __restrict__ weights,
                            const float* __restrict__ w_lin,
                            const float* __restrict__ w_deg1,
                            const float* __restrict__ nfeat) {
    int idx = blockIdx.x * 256 + threadIdx.x;
    if (idx < 8192) {
        const int lane = idx & 31;
        const int nfp  = (idx >> 5) & 3;
        const int kc   = (idx >> 7) & 3;
        const int ce = nfp * 16 + (lane >> 2);
        const int co = ce + 8;
        const int kb = kc * 16 + (lane & 3) * 2;
        {
            int a = idx >> 9;
            uint4 v;
            v.x = pack_h2(weights[(((kb + 0) << 6) + ce) * 16 + a],
                          weights[(((kb + 1) << 6) + ce) * 16 + a]);
            v.y = pack_h2(weights[(((kb + 8) << 6) + ce) * 16 + a],
                          weights[(((kb + 9) << 6) + ce) * 16 + a]);
            v.z = pack_h2(weights[(((kb + 0) << 6) + co) * 16 + a],
                          weights[(((kb + 1) << 6) + co) * 16 + a]);
            v.w = pack_h2(weights[(((kb + 8) << 6) + co) * 16 + a],
                          weights[(((kb + 9) << 6) + co) * 16 + a]);
            g_W1f[idx] = v;
        }
        if (idx < 512) {
            const float* se = w_lin + ce * 64;
            const float* so = w_lin + co * 64;
            uint4 v;
            v.x = pack_h2(se[kb], se[kb + 1]);
            v.y = pack_h2(se[kb + 8], se[kb + 9]);
            v.z = pack_h2(so[kb], so[kb + 1]);
            v.w = pack_h2(so[kb + 8], so[kb + 9]);
            g_W2f[idx] = v;
        }
        if (idx < 1024) {
            int ch = idx >> 9;
            const float* se = w_deg1 + ce * 128 + ch * 64;
            const float* so = w_deg1 + co * 128 + ch * 64;
            uint4 v;
            v.x = pack_h2(se[kb], se[kb + 1]);
            v.y = pack_h2(se[kb + 8], se[kb + 9]);
            v.z = pack_h2(so[kb], so[kb + 1]);
            v.w = pack_h2(so[kb + 8], so[kb + 9]);
            g_W3f[idx] = v;
        }
    } else {
        int j = idx - 8192;                 // 0 .. N_NODES*8-1
        if (j < N_NODES * 8) {
            const float4* src = (const float4*)(nfeat) + (size_t)j * 2;
            float4 a = src[0], b = src[1];
            uint4 v;
            v.x = pack_h2(a.x, a.y); v.y = pack_h2(a.z, a.w);
            v.z = pack_h2(b.x, b.y); v.w = pack_h2(b.z, b.w);
            g_nfh[j] = v;
        }
    }
}

// ============================================================================
// fused: warp-specialized, fp16, decoupled named-barrier pipeline (4 buffers)
// ============================================================================
__global__ __launch_bounds__(256, 2)
void fused_kernel(const float* __restrict__ degs,
                  const float* __restrict__ n2p_val,
                  const float* __restrict__ e2p_val,
                  const float* __restrict__ pool_val,
                  const float* __restrict__ bias,
                  const float* __restrict__ w_deg0,
                  const float* __restrict__ b_deg0,
                  const float* __restrict__ b_deg1,
                  const float* __restrict__ b_lin,
                  const float* __restrict__ bond_emb,
                  const int*   __restrict__ edge_feat_idx,
                  const int*   __restrict__ n2p_col,
                  const int*   __restrict__ e2p_col,
                  const int*   __restrict__ pool_row,
                  float*       __restrict__ out) {
    extern __shared__ char sm[];
    const uint32_t SB = s2u(sm);
    const int tid = threadIdx.x;
    const int warp = tid >> 5, lane = tid & 31;
    const int p0 = blockIdx.x * PT;

    uint4* s_bondh = (uint4*)(sm + SBOND);
    float* s_ds   = (float*)(sm + SDS);
    float* s_wd0  = (float*)(sm + SWD0);
    float* s_bd0  = (float*)(sm + SBD0);
    float* s_bia  = (float*)(sm + SBIA);
    float* s_bli  = (float*)(sm + SBLI);
    float* s_bd1  = (float*)(sm + SBD1);
    float* s_pv   = (float*)(sm + SPV);
    int*   s_pr   = (int*)(sm + SPR);

    if (tid < 32) {   // bond_emb -> fp16, 4 rows x 8 uint4
        int row = tid >> 3, c8 = tid & 7;
        const float* s = bond_emb + row * 64 + c8 * 8;
        uint4 v;
        v.x = pack_h2(s[0], s[1]); v.y = pack_h2(s[2], s[3]);
        v.z = pack_h2(s[4], s[5]); v.w = pack_h2(s[6], s[7]);
        s_bondh[tid] = v;
    }
    for (int i = tid; i < 512; i += 256) s_wd0[i] = w_deg0[i];
    if (tid < 128) s_bd0[tid] = b_deg0[tid];
    if (tid < 64) { s_bia[tid] = bias[tid]; s_bli[tid] = b_lin[tid]; s_bd1[tid] = b_deg1[tid]; }
    __syncthreads();

    const int rbase = (warp & 3) * 32;

    float acc1[2][8][4];
    #pragma unroll
    for (int m = 0; m < 2; m++)
        #pragma unroll
        for (int n = 0; n < 8; n++)
            #pragma unroll
            for (int j = 0; j < 4; j++) acc1[m][n][j] = 0.f;

    const int p = tid - 128;                 // producer row id (warp>=4)
    const bool valid = (p0 + p) < P_PERM;
    const int pc = valid ? (p0 + p) : (P_PERM - 1);

    int ncs[4], ecs[4];
    float vns[4], ves[4];

    // ======== mainloop: 8 epochs x 2 slices, decoupled named barriers ========
    // pair b (buffers 2b,2b+1) filled at epoch e (b=e&1), consumed at e+1.
    #pragma unroll
    for (int e = 0; e < 8; e++) {
        if (warp >= 4) {
            const int b = e & 1;
            if ((b) == 0) {                  // load 4-slice index group
                int g = e >> 1;
                int4 nc4 = ((const int4*)n2p_col)[pc * 4 + g];
                int4 ec4 = ((const int4*)e2p_col)[pc * 4 + g];
                float4 vn4 = ((const float4*)n2p_val)[pc * 4 + g];
                float4 ve4 = ((const float4*)e2p_val)[pc * 4 + g];
                ncs[0] = nc4.x; ncs[1] = nc4.y; ncs[2] = nc4.z; ncs[3] = nc4.w;
                ecs[0] = ec4.x; ecs[1] = ec4.y; ecs[2] = ec4.z; ecs[3] = ec4.w;
                vns[0] = vn4.x; vns[1] = vn4.y; vns[2] = vn4.z; vns[3] = vn4.w;
                ves[0] = ve4.x; ves[1] = ve4.y; ves[2] = ve4.z; ves[3] = ve4.w;
            }
            if (e >= 2) BAR_SYNC(BAR_FREE0 + b);   // wait pair free
            #pragma unroll
            for (int s = 0; s < 2; s++) {
                const int a = 2 * e + s;
                const int ai = a & 3;
                int nc = ncs[ai];
                int bj = edge_feat_idx[ecs[ai]];
                float vn = valid ? vns[ai] : 0.f;
                float ve = valid ? ves[ai] : 0.f;
                if (ai == (a >> 2)) s_ds[p * 4 + (a >> 2)] = vn * degs[nc]; // a%5==0
                char* xh = sm + (2 * b + s) * 16384;
                const int r0 = (warp - 4) * 32;
                #pragma unroll
                for (int pass = 0; pass < 8; pass++) {
                    int src = pass * 4 + (lane >> 3);
                    int   nc_r = __shfl_sync(FULLM, nc, src);
                    int   bj_r = __shfl_sync(FULLM, bj, src);
                    float vn_r = __shfl_sync(FULLM, vn, src);
                    float ve_r = __shfl_sync(FULLM, ve, src);
                    int row = r0 + pass * 4 + (lane >> 3);
                    uint4 nv = g_nfh[(size_t)nc_r * 8 + (lane & 7)];     // 1 LDG.128
                    uint4 bv = s_bondh[bj_r * 8 + (lane & 7)];           // 1 LDS.128
                    __half2 vn2 = __float2half2_rn(vn_r);
                    __half2 ve2 = __float2half2_rn(ve_r);
                    uint4 v;
                    *(__half2*)&v.x = __hfma2(vn2, *(const __half2*)&nv.x,
                                              __hmul2(ve2, *(const __half2*)&bv.x));
                    *(__half2*)&v.y = __hfma2(vn2, *(const __half2*)&nv.y,
                                              __hmul2(ve2, *(const __half2*)&bv.y));
                    *(__half2*)&v.z = __hfma2(vn2, *(const __half2*)&nv.z,
                                              __hmul2(ve2, *(const __half2*)&bv.z));
                    *(__half2*)&v.w = __hfma2(vn2, *(const __half2*)&nv.w,
                                              __hmul2(ve2, *(const __half2*)&bv.w));
                    uint32_t off = SWZ((uint32_t)row * 128 + ((lane & 7) << 4));
                    *(uint4*)(xh + off) = v;
                }
            }
            BAR_ARRIVE(BAR_FULL0 + b);             // pair filled
        } else if (e > 0) {
            const int b = (e - 1) & 1;
            BAR_SYNC(BAR_FULL0 + b);               // wait pair full
            #pragma unroll
            for (int s = 0; s < 2; s++) {
                const int a = 2 * (e - 1) + s;
                gemm_tile<4>(acc1, SB + (2 * b + s) * 16384, g_W1f + a * 512, 0, rbase, lane);
            }
            BAR_ARRIVE(BAR_FREE0 + b);             // pair free
        }
    }

    // ===================== epilogue phase A ==================================
    // consumers: sync FULL1, gemm slices 14 (XB2), 15 (XB3); relu(acc1+bias)->XB0 (own rows)
    // producers: sync FREE0, t0 -> XB1, pool staging
    if (warp < 4) {
        BAR_SYNC(BAR_FULL1);
        gemm_tile<4>(acc1, SB + XB2, g_W1f + 14 * 512, 0, rbase, lane);
        gemm_tile<4>(acc1, SB + XB3, g_W1f + 15 * 512, 0, rbase, lane);
        #pragma unroll
        for (int mt = 0; mt < 2; mt++)
            #pragma unroll
            for (int nf = 0; nf < 8; nf++) {
                int c0 = nf * 8 + (lane & 3) * 2;
                #pragma unroll
                for (int pr2 = 0; pr2 < 2; pr2++) {
                    int row = rbase + mt * 16 + (lane >> 2) + pr2 * 8;
                    float f0 = fmaxf(acc1[mt][nf][pr2 * 2 + 0] + s_bia[c0], 0.f);
                    float f1 = fmaxf(acc1[mt][nf][pr2 * 2 + 1] + s_bia[c0 + 1], 0.f);
                    uint32_t off = SWZ((uint32_t)row * 128 + (uint32_t)c0 * 2);
                    *(uint32_t*)(sm + XB0 + off) = pack_h2(f0, f1);
                }
            }
    } else {
        BAR_SYNC(BAR_FREE0);
        float4 dv = *(const float4*)&s_ds[p * 4];
        #pragma unroll
        for (int g = 0; g < 8; g++) {
            float f[8];
            #pragma unroll
            for (int j = 0; j < 8; j++) {
                int k = g * 8 + j;
                float4 w = *(const float4*)&s_wd0[k * 4];
                f[j] = fmaxf(dv.x * w.x + dv.y * w.y + dv.z * w.z + dv.w * w.w + s_bd0[k], 0.f);
            }
            uint4 v;
            v.x = pack_h2(f[0], f[1]); v.y = pack_h2(f[2], f[3]);
            v.z = pack_h2(f[4], f[5]); v.w = pack_h2(f[6], f[7]);
            uint32_t off = SWZ((uint32_t)p * 128 + g * 16);
            *(uint4*)(sm + XB1 + off) = v;
        }
        s_pv[p] = valid ? pool_val[p0 + p] : 0.f;
        s_pr[p] = valid ? pool_row[p0 + p] : 0;
    }
    __syncthreads();

    // ===================== epilogue phase B ==================================
    // consumers: acc2 = relu(h) @ W2^T (reads XB0 own rows); producers: t1 -> XB2
    float acc2[2][8][4];
    if (warp < 4) {
        #pragma unroll
        for (int m = 0; m < 2; m++)
            #pragma unroll
            for (int n = 0; n < 8; n++)
                #pragma unroll
                for (int j = 0; j < 4; j++) acc2[m][n][j] = 0.f;
        gemm_tile<4>(acc2, SB + XB0, g_W2f, 0, rbase, lane);
    } else {
        float4 dv = *(const float4*)&s_ds[p * 4];
        #pragma unroll
        for (int g = 0; g < 8; g++) {
            float f[8];
            #pragma unroll
            for (int j = 0; j < 8; j++) {
                int k = 64 + g * 8 + j;
                float4 w = *(const float4*)&s_wd0[k * 4];
                f[j] = fmaxf(dv.x * w.x + dv.y * w.y + dv.z * w.z + dv.w * w.w + s_bd0[k], 0.f);
            }
            uint4 v;
            v.x = pack_h2(f[0], f[1]); v.y = pack_h2(f[2], f[3]);
            v.z = pack_h2(f[4], f[5]); v.w = pack_h2(f[6], f[7]);
            uint32_t off = SWZ((uint32_t)p * 128 + g * 16);
            *(uint4*)(sm + XB2 + off) = v;
        }
    }
    __syncthreads();

    // ===================== epilogue phase C: gate, combine, scatter ==========
    if (warp < 4) {
        #pragma unroll
        for (int half = 0; half < 2; half++) {
            float acc3[2][4][4];
            #pragma unroll
            for (int m = 0; m < 2; m++)
                #pragma unroll
                for (int n = 0; n < 4; n++)
                    #pragma unroll
                    for (int j = 0; j < 4; j++) acc3[m][n][j] = 0.f;
            gemm_tile<2>(acc3, SB + XB1, g_W3f, half * 2, rbase, lane);        // t0 x W3 chunk0
            gemm_tile<2>(acc3, SB + XB2, g_W3f + 512, half * 2, rbase, lane);  // t1 x W3 chunk1
            #pragma unroll
            for (int mt = 0; mt < 2; mt++)
                #pragma unroll
                for (int fn = 0; fn < 4; fn++) {
                    int nf = half * 4 + fn;
                    int c0 = nf * 8 + (lane & 3) * 2;
                    #pragma unroll
                    for (int pr2 = 0; pr2 < 2; pr2++) {
                        int row = rbase + mt * 16 + (lane >> 2) + pr2 * 8;
                        if (p0 + row < P_PERM) {
                            float pv = s_pv[row];
                            int pr = s_pr[row];
                            float h2a = acc2[mt][nf][pr2 * 2 + 0] + s_bli[c0];
                            float h2b = acc2[mt][nf][pr2 * 2 + 1] + s_bli[c0 + 1];
                            float ga  = acc3[mt][fn][pr2 * 2 + 0] + s_bd1[c0];
                            float gb  = acc3[mt][fn][pr2 * 2 + 1] + s_bd1[c0 + 1];
                            atomicAdd(&out[((size_t)pr << 6) + c0],     pv * h2a * ga);
                            atomicAdd(&out[((size_t)pr << 6) + c0 + 1], pv * h2b * gb);
                        }
                    }
                }
        }
    }
}

// ============================================================================
extern "C" void kernel_launch(void* const* d_in, const int* in_sizes, int n_in,
                              void* d_out, int out_size) {
    const float* nfeat         = (const float*)d_in[0];
    const float* degs          = (const float*)d_in[1];
    const float* n2p_val       = (const float*)d_in[2];
    const float* e2p_val       = (const float*)d_in[3];
    const float* pool_val      = (const float*)d_in[4];
    const float* weights       = (const float*)d_in[5];
    const float* bias          = (const float*)d_in[6];
    const float* w_deg0        = (const float*)d_in[7];
    const float* b_deg0        = (const float*)d_in[8];
    const float* w_deg1        = (const float*)d_in[9];
    const float* b_deg1        = (const float*)d_in[10];
    const float* w_lin         = (const float*)d_in[11];
    const float* b_lin         = (const float*)d_in[12];
    const float* bond_emb      = (const float*)d_in[13];
    const int*   edge_feat_idx = (const int*)d_in[14];
    const int*   n2p_col       = (const int*)d_in[16];
    const int*   e2p_col       = (const int*)d_in[18];
    const int*   pool_row      = (const int*)d_in[19];
    float* out = (float*)d_out;

    cudaMemsetAsync(d_out, 0, (size_t)out_size * sizeof(float), 0);
    prep_kernel<<<(8192 + N_NODES * 8 + 255) / 256, 256>>>(weights, w_lin, w_deg1, nfeat);

    cudaFuncSetAttribute(fused_kernel, cudaFuncAttributeMaxDynamicSharedMemorySize, SMEM_BYTES);
    fused_kernel<<<NTILES, 256, SMEM_BYTES>>>(degs, n2p_val, e2p_val, pool_val,
                                              bias, w_deg0, b_deg0, b_deg1, b_lin,
                                              bond_emb, edge_feat_idx, n2p_col, e2p_col,
                                              pool_row, out);
}